// round 13
// baseline (speedup 1.0000x reference)
#include <cuda_runtime.h>
#include <cuda_fp16.h>
#include <math.h>
#include <stdint.h>

#define NF 3000
#define NB 1500
#define RAD2 9.0f
#define INV_R (1.0f/3.0f)
#define CAP 256
#define EPSF 1e-8f
#define FOUR_OVER_PI 1.2732395447351628f

// ---------------- static device scratch ----------------
__device__ float g_p1[NF*3];
__device__ float g_feat0[NF*9];
__device__ int   g_fcnt[NF];
__device__ int   g_fidx[NF*64];
__device__ int   g_fbase[NF*64];
__device__ float g_fw8[NF*512];
__device__ int   g_bcnt[NF];
__device__ int   g_bidx[NF*64];
__device__ int   g_bbase[NF*64];
__device__ float g_bw8[NF*512];
__device__ float g_A0[9000*192];
__device__ float g_Abox[NF*64];
__device__ __half g_Ah[(size_t)9088*6400];
__device__ __half g_Bh[64*14592];
__device__ __half g_Bl[64*14592];
__device__ float g_cf[9000*32];
__device__ float g_co[NF*32];
__device__ float g_out1[9000*96];
__device__ float g_out2[9000*96];

// ---------------- helpers ----------------
__device__ __forceinline__ uint32_t smem_u32(const void* p){
    uint32_t a;
    asm("{ .reg .u64 t; cvta.to.shared.u64 t, %1; cvt.u32.u64 %0, t; }" : "=r"(a) : "l"(p));
    return a;
}
__device__ __forceinline__ void ldsm_x4(uint32_t& r0, uint32_t& r1, uint32_t& r2, uint32_t& r3, uint32_t addr){
    asm volatile("ldmatrix.sync.aligned.m8n8.x4.shared.b16 {%0,%1,%2,%3}, [%4];"
        : "=r"(r0), "=r"(r1), "=r"(r2), "=r"(r3) : "r"(addr));
}
__device__ __forceinline__ void ldsm_x2(uint32_t& r0, uint32_t& r1, uint32_t addr){
    asm volatile("ldmatrix.sync.aligned.m8n8.x2.shared.b16 {%0,%1}, [%2];"
        : "=r"(r0), "=r"(r1) : "r"(addr));
}
__device__ __forceinline__ void mma_f16(float* c, const uint32_t* a, const uint32_t* b){
    asm volatile("mma.sync.aligned.m16n8k16.row.col.f32.f16.f16.f32 "
        "{%0,%1,%2,%3}, {%4,%5,%6,%7}, {%8,%9}, {%0,%1,%2,%3};"
        : "+f"(c[0]), "+f"(c[1]), "+f"(c[2]), "+f"(c[3])
        : "r"(a[0]), "r"(a[1]), "r"(a[2]), "r"(a[3]), "r"(b[0]), "r"(b[1]));
}

// ---------------- geometry ----------------
__device__ __forceinline__ float sgnf(float v){ return (v>0.f)?1.f:((v<0.f)?-1.f:0.f); }

__device__ __forceinline__ void ball_to_cube(float x,float y,float z,float&obx,float&oby,float&obz){
    float sq = x*x+y*y+z*z;
    float norm = sqrtf(fmaxf(sq,EPSF));
    float xy_sq = x*x+y*y;
    bool polar = (1.25f*z*z) > xy_sq;
    float s_p = sqrtf(3.0f*norm/(norm+fabsf(z)+EPSF));
    float s_e = norm / sqrtf(fmaxf(xy_sq,EPSF));
    float cx = polar ? x*s_p : x*s_e;
    float cy = polar ? y*s_p : y*s_e;
    float cz = polar ? sgnf(z)*norm : 1.5f*z;
    float nxy = sqrtf(fmaxf(cx*cx+cy*cy,EPSF));
    bool xdom = fabsf(cy) <= fabsf(cx);
    float sx = (fabsf(cx) > EPSF) ? cx : 1.0f;
    float sy = (fabsf(cy) > EPSF) ? cy : 1.0f;
    float bx1 = sgnf(cx)*nxy;
    float by1 = bx1*FOUR_OVER_PI*atanf(cy/sx);
    float by2 = sgnf(cy)*nxy;
    float bx2 = by2*FOUR_OVER_PI*atanf(cx/sy);
    float bx = xdom ? bx1 : bx2;
    float by = xdom ? by1 : by2;
    if (cx*cx+cy*cy < EPSF){ bx=0.f; by=0.f; }
    if (sq < EPSF){ bx=0.f; by=0.f; cz=0.f; }
    obx=bx; oby=by; obz=cz;
}

// ---------------- prep ----------------
__global__ void prep_kernel(const float* __restrict__ p0,const float* __restrict__ v0,
                            const float* __restrict__ a,const float* __restrict__ other,
                            const float* __restrict__ v0e,
                            float* __restrict__ p1,float* __restrict__ feat0,
                            float* __restrict__ outState){
    int i = blockIdx.x*blockDim.x + threadIdx.x;
    if (i >= NF) return;
#pragma unroll
    for (int d=0; d<3; d++){
        float vv0 = v0[i*3+d];
        float v1  = vv0 + 0.1f*a[i*3+d];
        float pp1 = p0[i*3+d] + 0.1f*(vv0+v1)*0.5f;
        p1[i*3+d]        = pp1;
        feat0[i*9+d]     = v1;
        feat0[i*9+3+d]   = other[i*3+d];
        feat0[i*9+6+d]   = v0e[i*3+d];
        outState[i*3+d]  = v0e[i*3+d];
    }
}

// ---------------- neighbor search ----------------
__global__ void neigh_kernel(const float* __restrict__ pin, int Mp,
                             const float* __restrict__ pout,
                             const float* __restrict__ mask, int selfEx,
                             int* __restrict__ cntO, int* __restrict__ idxO,
                             int* __restrict__ baseO, float* __restrict__ w8O){
    __shared__ float cd2[CAP];
    __shared__ int   cid[CAP];
    __shared__ unsigned long long keys[CAP];
    __shared__ int scnt;
    __shared__ int   sM[64];
    __shared__ int   sB[64];
    __shared__ float sW8[64*8];
    __shared__ unsigned skey[64];
    int n = blockIdx.x, tid = threadIdx.x;
    float qx = pout[n*3], qy = pout[n*3+1], qz = pout[n*3+2];
    if (tid==0) scnt = 0;
    __syncthreads();
    for (int m = tid; m < Mp; m += blockDim.x){
        if (selfEx && m==n) continue;
        if (mask && !(mask[m] > 0.f)) continue;
        float dx = pin[m*3]-qx, dy = pin[m*3+1]-qy, dz = pin[m*3+2]-qz;
        float d2 = dx*dx + dy*dy + dz*dz;
        if (d2 <= RAD2){
            int p = atomicAdd(&scnt, 1);
            if (p < CAP){ cd2[p]=d2; cid[p]=m; }
        }
    }
    __syncthreads();
    int cn = min(scnt, CAP);
    for (int t = tid; t < CAP; t += blockDim.x)
        keys[t] = (t < cn) ? ((((unsigned long long)__float_as_uint(cd2[t]))<<32) | (unsigned)cid[t])
                           : 0xFFFFFFFFFFFFFFFFull;
    __syncthreads();
    for (int k = 2; k <= CAP; k <<= 1){
        for (int j = k>>1; j > 0; j >>= 1){
            if (tid < 128){
                int i = ((tid & ~(j-1)) << 1) | (tid & (j-1));
                int ixj = i | j;
                bool asc = ((i & k) == 0);
                unsigned long long av = keys[i], bv = keys[ixj];
                if ((av > bv) == asc){ keys[i]=bv; keys[ixj]=av; }
            }
            __syncthreads();
        }
    }
    int keep = min(cn, 64);
    if (tid==0) cntO[n] = keep;
    for (int t = tid; t < keep; t += blockDim.x){
        unsigned long long key = keys[t];
        int m = (int)(key & 0xFFFFFFFFull);
        float dx = pin[m*3]-qx, dy = pin[m*3+1]-qy, dz = pin[m*3+2]-qz;
        float ux = dx*INV_R, uy = dy*INV_R, uz = dz*INV_R;
        float r2 = ux*ux + uy*uy + uz*uz;
        float t1 = 1.f - r2;
        float win = fminf(fmaxf(t1*t1*t1, 0.f), 1.f);
        float bx, by, bz;
        ball_to_cube(ux, uy, uz, bx, by, bz);
        float cxx = fminf(fmaxf((bx*0.5f+0.5f)*3.f, 0.f), 3.f);
        float cyy = fminf(fmaxf((by*0.5f+0.5f)*3.f, 0.f), 3.f);
        float czz = fminf(fmaxf((bz*0.5f+0.5f)*3.f, 0.f), 3.f);
        int c0x = min((int)floorf(cxx), 2);
        int c0y = min((int)floorf(cyy), 2);
        int c0z = min((int)floorf(czz), 2);
        float fx = cxx - (float)c0x, fy = cyy - (float)c0y, fz = czz - (float)c0z;
        sM[t] = m;
        sB[t] = (c0x*4 + c0y)*4 + c0z;
        float gx[2] = {1.f-fx, fx}, gy[2] = {1.f-fy, fy}, gz[2] = {1.f-fz, fz};
        int jj = 0;
        for (int i2=0;i2<2;i2++) for (int j2=0;j2<2;j2++) for (int l2=0;l2<2;l2++)
            sW8[t*8 + (jj++)] = gx[i2]*gy[j2]*gz[l2]*win;
    }
    for (int t = tid; t < 64; t += blockDim.x)
        skey[t] = (t < keep) ? (unsigned)((sB[t] << 6) | t) : 0xFFFFFFFFu;
    __syncthreads();
    for (int k = 2; k <= 64; k <<= 1){
        for (int j = k>>1; j > 0; j >>= 1){
            if (tid < 32){
                int i = ((tid & ~(j-1)) << 1) | (tid & (j-1));
                int ixj = i | j;
                bool asc = ((i & k) == 0);
                unsigned av = skey[i], bv = skey[ixj];
                if ((av > bv) == asc){ skey[i]=bv; skey[ixj]=av; }
            }
            __syncthreads();
        }
    }
    for (int t = tid; t < keep; t += blockDim.x){
        int s = (int)(skey[t] & 63u);
        idxO[n*64+t]  = sM[s];
        baseO[n*64+t] = sB[s];
#pragma unroll
        for (int j=0;j<8;j++) w8O[n*512 + t*8 + j] = sW8[s*8 + j];
    }
}

__constant__ int c_coff[8] = {0,1,4,5,16,17,20,21};

// ---------------- scatter layer0 fluid (F=9) ----------------
__global__ void scatter9(const float* __restrict__ feats,
                         const int* __restrict__ cnt, const int* __restrict__ nidx,
                         const int* __restrict__ nbase, const float* __restrict__ nw8,
                         float* __restrict__ A){
    __shared__ float planes[8*576];
    __shared__ float sfeat[64*9];
    __shared__ float sW[512];
    __shared__ int   sBase[64];
    __shared__ int   sIdx[64];
    int n = blockIdx.x, tid = threadIdx.x;
    int cn = cnt[n];
    for (int e = tid; e < 8*576; e += 96) planes[e] = 0.f;
    if (tid < cn){ sIdx[tid] = nidx[n*64+tid]; sBase[tid] = nbase[n*64+tid]; }
    for (int e = tid; e < cn*8; e += 96) sW[e] = nw8[n*512+e];
    __syncthreads();
    for (int e = tid; e < cn*9; e += 96){
        int k = e/9, f = e-k*9;
        sfeat[e] = feats[(size_t)sIdx[k]*9 + f];
    }
    __syncthreads();
    if (tid < 72){
        int j = tid/9, f = tid - j*9;
        int off = c_coff[j];
        float r = 0.f; int prevb = -1;
        for (int k = 0; k < cn; k++){
            int b = sBase[k];
            if (b != prevb){
                if (prevb >= 0) planes[j*576 + (prevb+off)*9 + f] += r;
                prevb = b; r = 0.f;
            }
            r += sW[k*8+j]*sfeat[k*9+f];
        }
        if (prevb >= 0) planes[j*576 + (prevb+off)*9 + f] += r;
    }
    __syncthreads();
    for (int e = tid; e < 576; e += 96){
        int l = e/9, f = e-l*9;
        int s = f/3, c = f-s*3;
        float v = 0.f;
#pragma unroll
        for (int j=0;j<8;j++) v += planes[j*576+e];
        A[(size_t)(n*3+s)*192 + l*3 + c] = v;
    }
}

// ---------------- scatter box (F=1) ----------------
__global__ void scatter1(const float* __restrict__ feats,
                         const int* __restrict__ cnt, const int* __restrict__ nidx,
                         const int* __restrict__ nbase, const float* __restrict__ nw8,
                         float* __restrict__ A){
    __shared__ float planes[8*8*64];
    __shared__ float sF[8*64];
    __shared__ float sW[8*512];
    __shared__ int   sBase[8*64];
    __shared__ int   sCn[8];
    int tid = threadIdx.x, nb = blockIdx.x;
    for (int e = tid; e < 8*8*64; e += 64) planes[e] = 0.f;
    for (int e = tid; e < 8*64; e += 64){
        int q = e>>6, k = e&63;
        int n = nb*8+q;
        if (k==0) sCn[q] = cnt[n];
        int cnq = cnt[n];
        if (k < cnq){ sBase[e] = nbase[n*64+k]; sF[e] = feats[nidx[n*64+k]]; }
    }
    for (int e = tid; e < 8*512; e += 64){
        int q = e>>9, r = e&511;
        sW[e] = nw8[(size_t)(nb*8+q)*512 + r];
    }
    __syncthreads();
    {
        int q = tid>>3, j = tid&7;
        int off = c_coff[j];
        int cnq = sCn[q];
        float r = 0.f; int prevb = -1;
        for (int k = 0; k < cnq; k++){
            int b = sBase[q*64+k];
            if (b != prevb){
                if (prevb >= 0) planes[(q*8+j)*64 + prevb+off] += r;
                prevb = b; r = 0.f;
            }
            r += sW[q*512 + k*8 + j]*sF[q*64+k];
        }
        if (prevb >= 0) planes[(q*8+j)*64 + prevb+off] += r;
    }
    __syncthreads();
    for (int e = tid; e < 512; e += 64){
        int q = e>>6, l = e&63;
        float v = 0.f;
#pragma unroll
        for (int j=0;j<8;j++) v += planes[(q*8+j)*64 + l];
        A[(size_t)(nb*8+q)*64 + l] = v;
    }
}

// ---------------- scatter (big): emits fp16 A rows [cellacc | relu(h)] ----------------
__global__ void scatter_big(const float* __restrict__ feats, int F, int C,
                            const int* __restrict__ cnt, const int* __restrict__ nidx,
                            const int* __restrict__ nbase, const float* __restrict__ nw8,
                            __half* __restrict__ Ah, int Kp){
    extern __shared__ float acc[];
    __shared__ int sIdx[64]; __shared__ int sBase[64]; __shared__ float sW[512];
    float4* acc4 = (float4*)acc;
    int n = blockIdx.x, tid = threadIdx.x, bd = blockDim.x;
    int F4 = F >> 2;
    int cn = cnt[n];
    for (int e = tid; e < 64*F4; e += bd) acc4[e] = make_float4(0.f,0.f,0.f,0.f);
    for (int e = tid; e < cn; e += bd){ sIdx[e] = nidx[n*64+e]; sBase[e] = nbase[n*64+e]; }
    for (int e = tid; e < cn*8; e += bd) sW[e] = nw8[n*512+e];
    __syncthreads();
    int f4 = tid;
    if (f4 < F4){
        float4 r[8];
        int prevb = -1;
        for (int k = 0; k < cn; k++){
            int b = sBase[k];
            if (b != prevb){
                if (prevb >= 0){
#pragma unroll
                    for (int j=0;j<8;j++){
                        int ai = (prevb + c_coff[j])*F4 + f4;
                        float4 t = acc4[ai];
                        t.x += r[j].x; t.y += r[j].y; t.z += r[j].z; t.w += r[j].w;
                        acc4[ai] = t;
                    }
                }
                prevb = b;
#pragma unroll
                for (int j=0;j<8;j++) r[j] = make_float4(0.f,0.f,0.f,0.f);
            }
            float4 fv = ((const float4*)(feats + (size_t)sIdx[k]*F))[f4];
            fv.x = fmaxf(fv.x,0.f); fv.y = fmaxf(fv.y,0.f);
            fv.z = fmaxf(fv.z,0.f); fv.w = fmaxf(fv.w,0.f);
#pragma unroll
            for (int j=0;j<8;j++){
                float w = sW[k*8+j];
                r[j].x += w*fv.x; r[j].y += w*fv.y; r[j].z += w*fv.z; r[j].w += w*fv.w;
            }
        }
        if (prevb >= 0){
#pragma unroll
            for (int j=0;j<8;j++){
                int ai = (prevb + c_coff[j])*F4 + f4;
                float4 t = acc4[ai];
                t.x += r[j].x; t.y += r[j].y; t.z += r[j].z; t.w += r[j].w;
                acc4[ai] = t;
            }
        }
    }
    __syncthreads();
    for (int e4 = tid; e4 < 64*F4; e4 += bd){
        int l = e4 / F4, fl = e4 - l*F4;
        int f = fl*4;
        int s = f / C, c = f - s*C;
        float4 v = acc4[e4];
        size_t base = (size_t)(n*3+s)*Kp + l*C + c;
        *(__half2*)(Ah+base)   = __floats2half2_rn(v.x, v.y);
        *(__half2*)(Ah+base+2) = __floats2half2_rn(v.z, v.w);
    }
    for (int e = tid; e < 3*C; e += bd){
        int s = e / C, c = e - s*C;
        float v = fmaxf(feats[(size_t)n*F + s*C + c], 0.f);
        Ah[(size_t)(n*3+s)*Kp + 64*C + c] = __float2half_rn(v);
    }
}

// ---------------- B': [kc ; wd] -> [64][Kp] fp16 hi+lo (n-major, zero pad) ----------------
__global__ void convB(const float* __restrict__ kc, const float* __restrict__ wd,
                      int C, int Kp, __half* __restrict__ BhT, __half* __restrict__ BlT){
    int e = blockIdx.x*blockDim.x + threadIdx.x;
    if (e >= 64*Kp) return;
    int n = e / Kp, k = e - n*Kp;
    float v = 0.f;
    if (k < 64*C) v = kc[(size_t)k*64 + n];
    else if (k < 64*C + C) v = wd[(size_t)(k - 64*C)*64 + n];
    __half h = __float2half_rn(v);
    BhT[e] = h;
    BlT[e] = __float2half_rn(v - __half2float(h));
}

// ---------------- fp16 MMA GEMM, fused epilogue:
// out[M,64] = A[M,K] @ (Bh+Bl)[64,K]^T + bc + bd (+ prev)
// 64x64 CTA tile, 8 warps (warp = 32x16), KC=64 chunks double-buffered, splitK=1.
__global__ __launch_bounds__(256) void gemm64(const __half* __restrict__ Ah,
                                              const __half* __restrict__ Bh,
                                              const __half* __restrict__ Bl,
                                              const float* __restrict__ bc,
                                              const float* __restrict__ bd,
                                              const float* __restrict__ prev,
                                              float* __restrict__ out, int M, int K){
    extern __shared__ __half sm[];
    const int RS = 72;                 // 64 + 8 pad halves per row
    const int OFF_BH = 64*RS;          // 4608
    const int OFF_BL = 128*RS;         // 9216
    const int BUFSZ  = 192*RS;         // 13824 halves per buffer
    int tid = threadIdx.x;
    int bm = blockIdx.x*64;
    int T = K >> 6;

    int arow = tid >> 2, aq = tid & 3;   // 64 rows, 4 thr/row, 16 halves each
    const __half* AG  = Ah + (size_t)(bm+arow)*K + aq*16;
    const __half* BhG = Bh + (size_t)arow*K + aq*16;
    const __half* BlG = Bl + (size_t)arow*K + aq*16;

    uint32_t sbase = smem_u32(sm);
    int wid = tid >> 5, lane = tid & 31;
    int wm = wid & 1, wn = wid >> 1;     // rows: 2x32, cols: 4x16

    uint4 ra0, ra1, rh0, rh1, rl0, rl1;
    ra0 = *(const uint4*)(AG);      ra1 = *(const uint4*)(AG + 8);
    rh0 = *(const uint4*)(BhG);     rh1 = *(const uint4*)(BhG + 8);
    rl0 = *(const uint4*)(BlG);     rl1 = *(const uint4*)(BlG + 8);
    {
        __half* buf = sm;
        *(uint4*)(buf + arow*RS + aq*16)     = ra0;
        *(uint4*)(buf + arow*RS + aq*16 + 8) = ra1;
        *(uint4*)(buf + OFF_BH + arow*RS + aq*16)     = rh0;
        *(uint4*)(buf + OFF_BH + arow*RS + aq*16 + 8) = rh1;
        *(uint4*)(buf + OFF_BL + arow*RS + aq*16)     = rl0;
        *(uint4*)(buf + OFF_BL + arow*RS + aq*16 + 8) = rl1;
    }
    __syncthreads();

    float acc[2][2][4];
#pragma unroll
    for (int mt=0;mt<2;mt++)
#pragma unroll
        for (int nt=0;nt<2;nt++)
#pragma unroll
            for (int q=0;q<4;q++) acc[mt][nt][q] = 0.f;

    for (int t = 0; t < T; t++){
        if (t+1 < T){
            ra0 = *(const uint4*)(AG + (size_t)(t+1)*64);
            ra1 = *(const uint4*)(AG + (size_t)(t+1)*64 + 8);
            rh0 = *(const uint4*)(BhG + (size_t)(t+1)*64);
            rh1 = *(const uint4*)(BhG + (size_t)(t+1)*64 + 8);
            rl0 = *(const uint4*)(BlG + (size_t)(t+1)*64);
            rl1 = *(const uint4*)(BlG + (size_t)(t+1)*64 + 8);
        }
        uint32_t bufo = (uint32_t)((t & 1) * BUFSZ) * 2;
#pragma unroll
        for (int ks = 0; ks < 4; ks++){
            int k0 = ks*16;
            uint32_t af[2][4];
#pragma unroll
            for (int mt=0;mt<2;mt++){
                int row = wm*32 + mt*16 + (lane & 15);
                int col = k0 + (lane >> 4)*8;
                uint32_t addr = sbase + bufo + (uint32_t)(row*RS + col)*2;
                ldsm_x4(af[mt][0], af[mt][1], af[mt][2], af[mt][3], addr);
            }
            uint32_t bfh[2][2], bfl[2][2];
#pragma unroll
            for (int nt=0;nt<2;nt++){
                int row = wn*16 + nt*8 + (lane & 7);
                int col = k0 + ((lane >> 3) & 1)*8;
                uint32_t addr = sbase + bufo + (uint32_t)(OFF_BH + row*RS + col)*2;
                ldsm_x2(bfh[nt][0], bfh[nt][1], addr);
                ldsm_x2(bfl[nt][0], bfl[nt][1], addr + (OFF_BL-OFF_BH)*2);
            }
#pragma unroll
            for (int mt=0;mt<2;mt++)
#pragma unroll
                for (int nt=0;nt<2;nt++){
                    mma_f16(acc[mt][nt], af[mt], bfh[nt]);
                    mma_f16(acc[mt][nt], af[mt], bfl[nt]);
                }
        }
        if (t+1 < T){
            __half* buf = sm + ((t+1) & 1) * BUFSZ;
            *(uint4*)(buf + arow*RS + aq*16)     = ra0;
            *(uint4*)(buf + arow*RS + aq*16 + 8) = ra1;
            *(uint4*)(buf + OFF_BH + arow*RS + aq*16)     = rh0;
            *(uint4*)(buf + OFF_BH + arow*RS + aq*16 + 8) = rh1;
            *(uint4*)(buf + OFF_BL + arow*RS + aq*16)     = rl0;
            *(uint4*)(buf + OFF_BL + arow*RS + aq*16 + 8) = rl1;
            __syncthreads();
        }
    }
#pragma unroll
    for (int mt=0;mt<2;mt++){
#pragma unroll
        for (int nt=0;nt<2;nt++){
            int r0 = bm + wm*32 + mt*16 + (lane >> 2);
            int c0 = wn*16 + nt*8 + (lane & 3)*2;
            float b0 = bc[c0] + bd[c0], b1 = bc[c0+1] + bd[c0+1];
            if (r0 < M){
                float v0 = acc[mt][nt][0] + b0, v1 = acc[mt][nt][1] + b1;
                if (prev){ v0 += prev[(size_t)r0*64 + c0]; v1 += prev[(size_t)r0*64 + c0 + 1]; }
                *(float2*)&out[(size_t)r0*64 + c0] = make_float2(v0, v1);
            }
            int r1 = r0 + 8;
            if (r1 < M){
                float v0 = acc[mt][nt][2] + b0, v1 = acc[mt][nt][3] + b1;
                if (prev){ v0 += prev[(size_t)r1*64 + c0]; v1 += prev[(size_t)r1*64 + c0 + 1]; }
                *(float2*)&out[(size_t)r1*64 + c0] = make_float2(v0, v1);
            }
        }
    }
}

// ---------------- fp32 GEMM N=32 (layer 0) ----------------
__global__ void gemm32(const float* __restrict__ A, const float* __restrict__ B,
                       float* __restrict__ Cc, int M, int N, int K){
    __shared__ float As[16][64];
    __shared__ float Bs[16][64];
    int tid = threadIdx.x;
    int bm = blockIdx.x * 64;
    int tm = tid >> 4, tn = tid & 15;
    float accv[4][4] = {};
    int arow = bm + (tid >> 2);
    int akq  = (tid & 3) * 4;
    int brow = tid >> 4;
    int bcol = (tid & 15) * 4;
    for (int k0 = 0; k0 < K; k0 += 16){
        float4 a4 = make_float4(0.f,0.f,0.f,0.f);
        if (arow < M) a4 = *(const float4*)(A + (size_t)arow*K + k0 + akq);
        float4 b4 = make_float4(0.f,0.f,0.f,0.f);
        if (bcol < N) b4 = *(const float4*)(B + (size_t)(k0+brow)*N + bcol);
        __syncthreads();
        int lr = tid >> 2;
        As[akq+0][lr] = a4.x; As[akq+1][lr] = a4.y; As[akq+2][lr] = a4.z; As[akq+3][lr] = a4.w;
        *(float4*)&Bs[brow][bcol] = b4;
        __syncthreads();
#pragma unroll
        for (int kk = 0; kk < 16; kk++){
            float4 av = *(const float4*)&As[kk][tm*4];
            float4 bv = *(const float4*)&Bs[kk][tn*4];
            float ar[4] = {av.x, av.y, av.z, av.w};
            float brr[4] = {bv.x, bv.y, bv.z, bv.w};
#pragma unroll
            for (int i=0;i<4;i++)
#pragma unroll
                for (int j=0;j<4;j++) accv[i][j] += ar[i]*brr[j];
        }
    }
#pragma unroll
    for (int i=0;i<4;i++){
        int r = bm + tm*4 + i;
        if (r >= M) continue;
#pragma unroll
        for (int j=0;j<4;j++){
            int c = tn*4 + j;
            if (c < N) Cc[(size_t)r*N + c] = accv[i][j];
        }
    }
}

// ---------------- fused layer-4 dot with biases: out = A(fp16) @ [kc;wd] + bc + bd ----------------
__global__ void dotn_f16(const __half* __restrict__ Ah,
                         const float* __restrict__ kcB, const float* __restrict__ wdB,
                         const float* __restrict__ bc, const float* __restrict__ bd,
                         int C, float* __restrict__ out, int M, int Kp){
    extern __shared__ float sBv[];
    int tid = threadIdx.x;
    int Kc = 64*C, Kt = Kc + C;
    for (int i = tid; i < Kc*3; i += blockDim.x) sBv[i] = kcB[i];
    for (int i = tid; i < C*3; i += blockDim.x) sBv[Kc*3 + i] = wdB[i];
    __syncthreads();
    int w = tid >> 5, lane = tid & 31;
    int r = blockIdx.x * 8 + w;
    if (r >= M) return;
    float a0=0.f, a1=0.f, a2=0.f;
    const __half* ap = Ah + (size_t)r*Kp;
    for (int k = lane*2; k < Kt; k += 64){
        __half2 h2 = *(const __half2*)(ap + k);
        float av0 = __half2float(h2.x);
        float av1 = __half2float(h2.y);
        a0 += av0 * sBv[k*3+0] + av1 * sBv[(k+1)*3+0];
        a1 += av0 * sBv[k*3+1] + av1 * sBv[(k+1)*3+1];
        a2 += av0 * sBv[k*3+2] + av1 * sBv[(k+1)*3+2];
    }
    for (int off=16; off; off>>=1){
        a0 += __shfl_down_sync(0xffffffffu, a0, off);
        a1 += __shfl_down_sync(0xffffffffu, a1, off);
        a2 += __shfl_down_sync(0xffffffffu, a2, off);
    }
    if (lane == 0){
        out[(size_t)r*3+0] = a0 + bc[0] + bd[0];
        out[(size_t)r*3+1] = a1 + bc[1] + bd[1];
        out[(size_t)r*3+2] = a2 + bc[2] + bd[2];
    }
}

// ---------------- elementwise ----------------
__global__ void combine0_kernel(const float* __restrict__ co, const float* __restrict__ cf,
                                const float* __restrict__ feat0,
                                const float* __restrict__ b0o, const float* __restrict__ b0f,
                                const float* __restrict__ wdf, const float* __restrict__ bdf,
                                float* __restrict__ out){
    int e = blockIdx.x*blockDim.x + threadIdx.x;
    if (e >= 9000*96) return;
    int row = e / 96, o = e - row*96;
    int n = row / 3;
    float v;
    if (o < 32) v = co[n*32+o] + b0o[o];
    else if (o < 64) v = cf[(size_t)row*32 + (o-32)] + b0f[o-32];
    else {
        int oo = o - 64;
        v = bdf[oo];
        for (int c=0;c<3;c++) v += feat0[row*3+c]*wdf[c*32+oo];
    }
    out[e] = v;
}

__global__ void final_kernel(const float* __restrict__ out4, const float* __restrict__ p1,
                             const float* __restrict__ p0, float* __restrict__ dout){
    int e = blockIdx.x*blockDim.x + threadIdx.x;
    if (e >= NF*3) return;
    int n = e/3, d = e - n*3;
    float pc0 = out4[(n*3+0)*3+d] * 0.25f * (1.0f/16.0f);
    float pc1 = out4[(n*3+1)*3+d] * 0.25f;
    float pc2 = out4[(n*3+2)*3+d] * 0.25f;
    float p_c = p1[e] + pc0;
    dout[e] = p_c;
    dout[9000 + e] = (p_c - p0[e]) / 0.1f;
    dout[18000 + n*6 + d]     = pc1;
    dout[18000 + n*6 + 3 + d] = pc2;
}

// ---------------- launch ----------------
extern "C" void kernel_launch(void* const* d_in, const int* in_sizes, int n_in,
                              void* d_out, int out_size){
    const float* v0e  = (const float*)d_in[1];
    const float* p0   = (const float*)d_in[2];
    const float* v0   = (const float*)d_in[3];
    const float* a    = (const float*)d_in[4];
    const float* other= (const float*)d_in[5];
    const float* box  = (const float*)d_in[6];
    const float* boxf = (const float*)d_in[7];
    const float* bmask= (const float*)d_in[9];
    const float* k0f  = (const float*)d_in[10];
    const float* b0f  = (const float*)d_in[11];
    const float* k0o  = (const float*)d_in[12];
    const float* b0o  = (const float*)d_in[13];
    const float* wdf  = (const float*)d_in[14];
    const float* bdf  = (const float*)d_in[15];
    const float *kc[4], *bcp[4], *wd[4], *bdp[4];
    if (in_sizes[18] == 262144){
        for (int i=0;i<4;i++){
            kc[i]=(const float*)d_in[16+2*i]; bcp[i]=(const float*)d_in[17+2*i];
            wd[i]=(const float*)d_in[24+2*i]; bdp[i]=(const float*)d_in[25+2*i];
        }
    } else {
        for (int i=0;i<4;i++){
            kc[i]=(const float*)d_in[16+4*i]; bcp[i]=(const float*)d_in[17+4*i];
            wd[i]=(const float*)d_in[18+4*i]; bdp[i]=(const float*)d_in[19+4*i];
        }
    }
    float* dout = (float*)d_out;

    float *p1, *feat0, *A0, *Abox, *cfb, *cob, *o1, *o2, *fw8, *bw8;
    __half *Ahp, *Bhp, *Blp;
    int *fcnt, *fidx, *fbase, *bcnt, *bidx, *bbase;
    cudaGetSymbolAddress((void**)&p1, g_p1);
    cudaGetSymbolAddress((void**)&feat0, g_feat0);
    cudaGetSymbolAddress((void**)&A0, g_A0);
    cudaGetSymbolAddress((void**)&Abox, g_Abox);
    cudaGetSymbolAddress((void**)&Ahp, g_Ah);
    cudaGetSymbolAddress((void**)&Bhp, g_Bh);
    cudaGetSymbolAddress((void**)&Blp, g_Bl);
    cudaGetSymbolAddress((void**)&cfb, g_cf);
    cudaGetSymbolAddress((void**)&cob, g_co);
    cudaGetSymbolAddress((void**)&o1, g_out1);
    cudaGetSymbolAddress((void**)&o2, g_out2);
    cudaGetSymbolAddress((void**)&fw8, g_fw8);
    cudaGetSymbolAddress((void**)&bw8, g_bw8);
    cudaGetSymbolAddress((void**)&fcnt, g_fcnt);
    cudaGetSymbolAddress((void**)&fidx, g_fidx);
    cudaGetSymbolAddress((void**)&fbase, g_fbase);
    cudaGetSymbolAddress((void**)&bcnt, g_bcnt);
    cudaGetSymbolAddress((void**)&bidx, g_bidx);
    cudaGetSymbolAddress((void**)&bbase, g_bbase);

    cudaFuncSetAttribute(scatter_big, cudaFuncAttributeMaxDynamicSharedMemorySize, 80000);
    cudaFuncSetAttribute(gemm64,      cudaFuncAttributeMaxDynamicSharedMemorySize, 56000);
    cudaFuncSetAttribute(dotn_f16,    cudaFuncAttributeMaxDynamicSharedMemorySize, 50000);

    int Kp[4]       = {6272, 4160, 4160, 4160};
    size_t BOff[3]  = {0, (size_t)64*6272, (size_t)64*6272 + (size_t)64*4160};
    int Cin[4]      = {96, 64, 64, 64};

    // weight-only conversions first (off the data-dependent chain)
    convB<<<(64*6272+255)/256, 256>>>(kc[0], wd[0], 96, 6272, Bhp + BOff[0], Blp + BOff[0]);
    convB<<<(64*4160+255)/256, 256>>>(kc[1], wd[1], 64, 4160, Bhp + BOff[1], Blp + BOff[1]);
    convB<<<(64*4160+255)/256, 256>>>(kc[2], wd[2], 64, 4160, Bhp + BOff[2], Blp + BOff[2]);

    prep_kernel<<<(NF+127)/128, 128>>>(p0, v0, a, other, v0e, p1, feat0, dout + 36000);
    neigh_kernel<<<NF, 256>>>(p1, NF, p1, nullptr, 1, fcnt, fidx, fbase, fw8);
    neigh_kernel<<<NF, 256>>>(box, NB, p1, bmask, 0, bcnt, bidx, bbase, bw8);

    // layer 0
    scatter9<<<NF, 96>>>(feat0, fcnt, fidx, fbase, fw8, A0);
    gemm32<<<(9000+63)/64, 256>>>(A0, k0f, cfb, 9000, 32, 192);
    scatter1<<<NF/8, 64>>>(boxf, bcnt, bidx, bbase, bw8, Abox);
    gemm32<<<(3000+63)/64, 256>>>(Abox, k0o, cob, 3000, 32, 64);
    combine0_kernel<<<(9000*96+255)/256, 256>>>(cob, cfb, feat0, b0o, b0f, wdf, bdf, o1);

    float* cur = o1; float* nxt = o2;
    for (int i=0;i<4;i++){
        int ci = Cin[i];
        int F = 3*ci, F4 = F/4;
        int bD = ((F4 + 31)/32)*32;
        scatter_big<<<NF, bD, (size_t)64*F*4>>>(cur, F, ci, fcnt, fidx, fbase, fw8, Ahp, Kp[i]);
        if (i < 3){
            gemm64<<<141, 256, 55296>>>(Ahp, Bhp + BOff[i], Blp + BOff[i],
                bcp[i], bdp[i], (i==1||i==2) ? cur : nullptr, nxt, 9000, Kp[i]);
        } else {
            dotn_f16<<<(9000+7)/8, 256, (size_t)4160*3*4>>>(Ahp, kc[3], wd[3],
                bcp[3], bdp[3], 64, nxt, 9000, Kp[3]);
        }
        float* t = cur; cur = nxt; nxt = t;
    }
    final_kernel<<<(NF*3+255)/256, 256>>>(cur, p1, p0, dout);
}

// round 14
// speedup vs baseline: 1.1148x; 1.1148x over previous
#include <cuda_runtime.h>
#include <cuda_fp16.h>
#include <math.h>
#include <stdint.h>

#define NF 3000
#define NB 1500
#define RAD2 9.0f
#define INV_R (1.0f/3.0f)
#define CAP 256
#define EPSF 1e-8f
#define FOUR_OVER_PI 1.2732395447351628f

// ---------------- static device scratch ----------------
__device__ float g_p1[NF*3];
__device__ float g_feat0[NF*9];
__device__ int   g_fcnt[NF];
__device__ int   g_fidx[NF*64];
__device__ int   g_fbase[NF*64];
__device__ float g_fw8[NF*512];
__device__ int   g_bcnt[NF];
__device__ int   g_bidx[NF*64];
__device__ int   g_bbase[NF*64];
__device__ float g_bw8[NF*512];
__device__ float g_A0[9000*192];
__device__ float g_Abox[NF*64];
__device__ __half g_Ah[(size_t)9088*6400];
__device__ __half g_Bh[64*14784];
__device__ __half g_Bl[64*14784];
__device__ float g_cf[9000*32];
__device__ float g_co[NF*32];
__device__ float g_oc[2*9000*64];
__device__ float g_out1[9000*96];
__device__ float g_out2[9000*96];

// ---------------- helpers ----------------
__device__ __forceinline__ uint32_t smem_u32(const void* p){
    uint32_t a;
    asm("{ .reg .u64 t; cvta.to.shared.u64 t, %1; cvt.u32.u64 %0, t; }" : "=r"(a) : "l"(p));
    return a;
}
__device__ __forceinline__ void ldsm_x4(uint32_t& r0, uint32_t& r1, uint32_t& r2, uint32_t& r3, uint32_t addr){
    asm volatile("ldmatrix.sync.aligned.m8n8.x4.shared.b16 {%0,%1,%2,%3}, [%4];"
        : "=r"(r0), "=r"(r1), "=r"(r2), "=r"(r3) : "r"(addr));
}
__device__ __forceinline__ void ldsm_x2(uint32_t& r0, uint32_t& r1, uint32_t addr){
    asm volatile("ldmatrix.sync.aligned.m8n8.x2.shared.b16 {%0,%1}, [%2];"
        : "=r"(r0), "=r"(r1) : "r"(addr));
}
__device__ __forceinline__ void mma_f16(float* c, const uint32_t* a, const uint32_t* b){
    asm volatile("mma.sync.aligned.m16n8k16.row.col.f32.f16.f16.f32 "
        "{%0,%1,%2,%3}, {%4,%5,%6,%7}, {%8,%9}, {%0,%1,%2,%3};"
        : "+f"(c[0]), "+f"(c[1]), "+f"(c[2]), "+f"(c[3])
        : "r"(a[0]), "r"(a[1]), "r"(a[2]), "r"(a[3]), "r"(b[0]), "r"(b[1]));
}

// ---------------- geometry ----------------
__device__ __forceinline__ float sgnf(float v){ return (v>0.f)?1.f:((v<0.f)?-1.f:0.f); }

__device__ __forceinline__ void ball_to_cube(float x,float y,float z,float&obx,float&oby,float&obz){
    float sq = x*x+y*y+z*z;
    float norm = sqrtf(fmaxf(sq,EPSF));
    float xy_sq = x*x+y*y;
    bool polar = (1.25f*z*z) > xy_sq;
    float s_p = sqrtf(3.0f*norm/(norm+fabsf(z)+EPSF));
    float s_e = norm / sqrtf(fmaxf(xy_sq,EPSF));
    float cx = polar ? x*s_p : x*s_e;
    float cy = polar ? y*s_p : y*s_e;
    float cz = polar ? sgnf(z)*norm : 1.5f*z;
    float nxy = sqrtf(fmaxf(cx*cx+cy*cy,EPSF));
    bool xdom = fabsf(cy) <= fabsf(cx);
    float sx = (fabsf(cx) > EPSF) ? cx : 1.0f;
    float sy = (fabsf(cy) > EPSF) ? cy : 1.0f;
    float bx1 = sgnf(cx)*nxy;
    float by1 = bx1*FOUR_OVER_PI*atanf(cy/sx);
    float by2 = sgnf(cy)*nxy;
    float bx2 = by2*FOUR_OVER_PI*atanf(cx/sy);
    float bx = xdom ? bx1 : bx2;
    float by = xdom ? by1 : by2;
    if (cx*cx+cy*cy < EPSF){ bx=0.f; by=0.f; }
    if (sq < EPSF){ bx=0.f; by=0.f; cz=0.f; }
    obx=bx; oby=by; obz=cz;
}

// ---------------- prep ----------------
__global__ void prep_kernel(const float* __restrict__ p0,const float* __restrict__ v0,
                            const float* __restrict__ a,const float* __restrict__ other,
                            const float* __restrict__ v0e,
                            float* __restrict__ p1,float* __restrict__ feat0,
                            float* __restrict__ outState){
    int i = blockIdx.x*blockDim.x + threadIdx.x;
    if (i >= NF) return;
#pragma unroll
    for (int d=0; d<3; d++){
        float vv0 = v0[i*3+d];
        float v1  = vv0 + 0.1f*a[i*3+d];
        float pp1 = p0[i*3+d] + 0.1f*(vv0+v1)*0.5f;
        p1[i*3+d]        = pp1;
        feat0[i*9+d]     = v1;
        feat0[i*9+3+d]   = other[i*3+d];
        feat0[i*9+6+d]   = v0e[i*3+d];
        outState[i*3+d]  = v0e[i*3+d];
    }
}

// ---------------- neighbor search ----------------
__global__ void neigh_kernel(const float* __restrict__ pin, int Mp,
                             const float* __restrict__ pout,
                             const float* __restrict__ mask, int selfEx,
                             int* __restrict__ cntO, int* __restrict__ idxO,
                             int* __restrict__ baseO, float* __restrict__ w8O){
    __shared__ float cd2[CAP];
    __shared__ int   cid[CAP];
    __shared__ unsigned long long keys[CAP];
    __shared__ int scnt;
    __shared__ int   sM[64];
    __shared__ int   sB[64];
    __shared__ float sW8[64*8];
    __shared__ unsigned skey[64];
    int n = blockIdx.x, tid = threadIdx.x;
    float qx = pout[n*3], qy = pout[n*3+1], qz = pout[n*3+2];
    if (tid==0) scnt = 0;
    __syncthreads();
    for (int m = tid; m < Mp; m += blockDim.x){
        if (selfEx && m==n) continue;
        if (mask && !(mask[m] > 0.f)) continue;
        float dx = pin[m*3]-qx, dy = pin[m*3+1]-qy, dz = pin[m*3+2]-qz;
        float d2 = dx*dx + dy*dy + dz*dz;
        if (d2 <= RAD2){
            int p = atomicAdd(&scnt, 1);
            if (p < CAP){ cd2[p]=d2; cid[p]=m; }
        }
    }
    __syncthreads();
    int cn = min(scnt, CAP);
    for (int t = tid; t < CAP; t += blockDim.x)
        keys[t] = (t < cn) ? ((((unsigned long long)__float_as_uint(cd2[t]))<<32) | (unsigned)cid[t])
                           : 0xFFFFFFFFFFFFFFFFull;
    __syncthreads();
    for (int k = 2; k <= CAP; k <<= 1){
        for (int j = k>>1; j > 0; j >>= 1){
            if (tid < 128){
                int i = ((tid & ~(j-1)) << 1) | (tid & (j-1));
                int ixj = i | j;
                bool asc = ((i & k) == 0);
                unsigned long long av = keys[i], bv = keys[ixj];
                if ((av > bv) == asc){ keys[i]=bv; keys[ixj]=av; }
            }
            __syncthreads();
        }
    }
    int keep = min(cn, 64);
    if (tid==0) cntO[n] = keep;
    for (int t = tid; t < keep; t += blockDim.x){
        unsigned long long key = keys[t];
        int m = (int)(key & 0xFFFFFFFFull);
        float dx = pin[m*3]-qx, dy = pin[m*3+1]-qy, dz = pin[m*3+2]-qz;
        float ux = dx*INV_R, uy = dy*INV_R, uz = dz*INV_R;
        float r2 = ux*ux + uy*uy + uz*uz;
        float t1 = 1.f - r2;
        float win = fminf(fmaxf(t1*t1*t1, 0.f), 1.f);
        float bx, by, bz;
        ball_to_cube(ux, uy, uz, bx, by, bz);
        float cxx = fminf(fmaxf((bx*0.5f+0.5f)*3.f, 0.f), 3.f);
        float cyy = fminf(fmaxf((by*0.5f+0.5f)*3.f, 0.f), 3.f);
        float czz = fminf(fmaxf((bz*0.5f+0.5f)*3.f, 0.f), 3.f);
        int c0x = min((int)floorf(cxx), 2);
        int c0y = min((int)floorf(cyy), 2);
        int c0z = min((int)floorf(czz), 2);
        float fx = cxx - (float)c0x, fy = cyy - (float)c0y, fz = czz - (float)c0z;
        sM[t] = m;
        sB[t] = (c0x*4 + c0y)*4 + c0z;
        float gx[2] = {1.f-fx, fx}, gy[2] = {1.f-fy, fy}, gz[2] = {1.f-fz, fz};
        int jj = 0;
        for (int i2=0;i2<2;i2++) for (int j2=0;j2<2;j2++) for (int l2=0;l2<2;l2++)
            sW8[t*8 + (jj++)] = gx[i2]*gy[j2]*gz[l2]*win;
    }
    for (int t = tid; t < 64; t += blockDim.x)
        skey[t] = (t < keep) ? (unsigned)((sB[t] << 6) | t) : 0xFFFFFFFFu;
    __syncthreads();
    for (int k = 2; k <= 64; k <<= 1){
        for (int j = k>>1; j > 0; j >>= 1){
            if (tid < 32){
                int i = ((tid & ~(j-1)) << 1) | (tid & (j-1));
                int ixj = i | j;
                bool asc = ((i & k) == 0);
                unsigned av = skey[i], bv = skey[ixj];
                if ((av > bv) == asc){ skey[i]=bv; skey[ixj]=av; }
            }
            __syncthreads();
        }
    }
    for (int t = tid; t < keep; t += blockDim.x){
        int s = (int)(skey[t] & 63u);
        idxO[n*64+t]  = sM[s];
        baseO[n*64+t] = sB[s];
#pragma unroll
        for (int j=0;j<8;j++) w8O[n*512 + t*8 + j] = sW8[s*8 + j];
    }
}

__constant__ int c_coff[8] = {0,1,4,5,16,17,20,21};

// ---------------- scatter layer0 fluid (F=9) ----------------
__global__ void scatter9(const float* __restrict__ feats,
                         const int* __restrict__ cnt, const int* __restrict__ nidx,
                         const int* __restrict__ nbase, const float* __restrict__ nw8,
                         float* __restrict__ A){
    __shared__ float planes[8*576];
    __shared__ float sfeat[64*9];
    __shared__ float sW[512];
    __shared__ int   sBase[64];
    __shared__ int   sIdx[64];
    int n = blockIdx.x, tid = threadIdx.x;
    int cn = cnt[n];
    for (int e = tid; e < 8*576; e += 96) planes[e] = 0.f;
    if (tid < cn){ sIdx[tid] = nidx[n*64+tid]; sBase[tid] = nbase[n*64+tid]; }
    for (int e = tid; e < cn*8; e += 96) sW[e] = nw8[n*512+e];
    __syncthreads();
    for (int e = tid; e < cn*9; e += 96){
        int k = e/9, f = e-k*9;
        sfeat[e] = feats[(size_t)sIdx[k]*9 + f];
    }
    __syncthreads();
    if (tid < 72){
        int j = tid/9, f = tid - j*9;
        int off = c_coff[j];
        float r = 0.f; int prevb = -1;
        for (int k = 0; k < cn; k++){
            int b = sBase[k];
            if (b != prevb){
                if (prevb >= 0) planes[j*576 + (prevb+off)*9 + f] += r;
                prevb = b; r = 0.f;
            }
            r += sW[k*8+j]*sfeat[k*9+f];
        }
        if (prevb >= 0) planes[j*576 + (prevb+off)*9 + f] += r;
    }
    __syncthreads();
    for (int e = tid; e < 576; e += 96){
        int l = e/9, f = e-l*9;
        int s = f/3, c = f-s*3;
        float v = 0.f;
#pragma unroll
        for (int j=0;j<8;j++) v += planes[j*576+e];
        A[(size_t)(n*3+s)*192 + l*3 + c] = v;
    }
}

// ---------------- scatter box (F=1) ----------------
__global__ void scatter1(const float* __restrict__ feats,
                         const int* __restrict__ cnt, const int* __restrict__ nidx,
                         const int* __restrict__ nbase, const float* __restrict__ nw8,
                         float* __restrict__ A){
    __shared__ float planes[8*8*64];
    __shared__ float sF[8*64];
    __shared__ float sW[8*512];
    __shared__ int   sBase[8*64];
    __shared__ int   sCn[8];
    int tid = threadIdx.x, nb = blockIdx.x;
    for (int e = tid; e < 8*8*64; e += 64) planes[e] = 0.f;
    for (int e = tid; e < 8*64; e += 64){
        int q = e>>6, k = e&63;
        int n = nb*8+q;
        if (k==0) sCn[q] = cnt[n];
        int cnq = cnt[n];
        if (k < cnq){ sBase[e] = nbase[n*64+k]; sF[e] = feats[nidx[n*64+k]]; }
    }
    for (int e = tid; e < 8*512; e += 64){
        int q = e>>9, r = e&511;
        sW[e] = nw8[(size_t)(nb*8+q)*512 + r];
    }
    __syncthreads();
    {
        int q = tid>>3, j = tid&7;
        int off = c_coff[j];
        int cnq = sCn[q];
        float r = 0.f; int prevb = -1;
        for (int k = 0; k < cnq; k++){
            int b = sBase[q*64+k];
            if (b != prevb){
                if (prevb >= 0) planes[(q*8+j)*64 + prevb+off] += r;
                prevb = b; r = 0.f;
            }
            r += sW[q*512 + k*8 + j]*sF[q*64+k];
        }
        if (prevb >= 0) planes[(q*8+j)*64 + prevb+off] += r;
    }
    __syncthreads();
    for (int e = tid; e < 512; e += 64){
        int q = e>>6, l = e&63;
        float v = 0.f;
#pragma unroll
        for (int j=0;j<8;j++) v += planes[(q*8+j)*64 + l];
        A[(size_t)(nb*8+q)*64 + l] = v;
    }
}

// ---------------- scatter (big): batched prefetch; A rows [cellacc | hh | hl] ----------------
__global__ void scatter_big(const float* __restrict__ feats, int F, int C,
                            const int* __restrict__ cnt, const int* __restrict__ nidx,
                            const int* __restrict__ nbase, const float* __restrict__ nw8,
                            __half* __restrict__ Ah, int Kp){
    extern __shared__ float acc[];
    __shared__ int sIdx[64]; __shared__ int sBase[64]; __shared__ float sW[512];
    float4* acc4 = (float4*)acc;
    int n = blockIdx.x, tid = threadIdx.x, bd = blockDim.x;
    int F4 = F >> 2;
    int cn = cnt[n];
    for (int e = tid; e < 64*F4; e += bd) acc4[e] = make_float4(0.f,0.f,0.f,0.f);
    for (int e = tid; e < cn; e += bd){ sIdx[e] = nidx[n*64+e]; sBase[e] = nbase[n*64+e]; }
    for (int e = tid; e < cn*8; e += bd) sW[e] = nw8[n*512+e];
    __syncthreads();
    int f4 = tid;
    if (f4 < F4){
        float4 r[8];
        int prevb = -1;
#pragma unroll
        for (int j=0;j<8;j++) r[j] = make_float4(0.f,0.f,0.f,0.f);
        for (int k0 = 0; k0 < cn; k0 += 8){
            int kb = min(8, cn - k0);
            float4 fv[8];
#pragma unroll
            for (int j=0;j<8;j++){
                if (j < kb){
                    float4 t = ((const float4*)(feats + (size_t)sIdx[k0+j]*F))[f4];
                    t.x = fmaxf(t.x,0.f); t.y = fmaxf(t.y,0.f);
                    t.z = fmaxf(t.z,0.f); t.w = fmaxf(t.w,0.f);
                    fv[j] = t;
                }
            }
#pragma unroll
            for (int j=0;j<8;j++){
                if (j < kb){
                    int b = sBase[k0+j];
                    if (b != prevb){
                        if (prevb >= 0){
#pragma unroll
                            for (int q=0;q<8;q++){
                                int ai = (prevb + c_coff[q])*F4 + f4;
                                float4 t = acc4[ai];
                                t.x += r[q].x; t.y += r[q].y; t.z += r[q].z; t.w += r[q].w;
                                acc4[ai] = t;
                            }
                        }
                        prevb = b;
#pragma unroll
                        for (int q=0;q<8;q++) r[q] = make_float4(0.f,0.f,0.f,0.f);
                    }
#pragma unroll
                    for (int q=0;q<8;q++){
                        float w = sW[(k0+j)*8+q];
                        r[q].x += w*fv[j].x; r[q].y += w*fv[j].y;
                        r[q].z += w*fv[j].z; r[q].w += w*fv[j].w;
                    }
                }
            }
        }
        if (prevb >= 0){
#pragma unroll
            for (int q=0;q<8;q++){
                int ai = (prevb + c_coff[q])*F4 + f4;
                float4 t = acc4[ai];
                t.x += r[q].x; t.y += r[q].y; t.z += r[q].z; t.w += r[q].w;
                acc4[ai] = t;
            }
        }
    }
    __syncthreads();
    for (int e4 = tid; e4 < 64*F4; e4 += bd){
        int l = e4 / F4, fl = e4 - l*F4;
        int f = fl*4;
        int s = f / C, c = f - s*C;
        float4 v = acc4[e4];
        size_t base = (size_t)(n*3+s)*Kp + l*C + c;
        *(__half2*)(Ah+base)   = __floats2half2_rn(v.x, v.y);
        *(__half2*)(Ah+base+2) = __floats2half2_rn(v.z, v.w);
    }
    // dense branch columns: hi and lo halves of relu(h)
    for (int e = tid; e < 3*C; e += bd){
        int s = e / C, c = e - s*C;
        float v = fmaxf(feats[(size_t)n*F + s*C + c], 0.f);
        __half hh = __float2half_rn(v);
        float lo = v - __half2float(hh);
        Ah[(size_t)(n*3+s)*Kp + 64*C + c]     = hh;
        Ah[(size_t)(n*3+s)*Kp + 64*C + C + c] = __float2half_rn(lo);
    }
}

// ---------------- B': [kc | wd | wd] -> [64][Kp] fp16 hi+lo (n-major, zero pad) ----------------
__global__ void convB(const float* __restrict__ kc, const float* __restrict__ wd,
                      int C, int Kp, __half* __restrict__ BhT, __half* __restrict__ BlT){
    int e = blockIdx.x*blockDim.x + threadIdx.x;
    if (e >= 64*Kp) return;
    int n = e / Kp, k = e - n*Kp;
    float v = 0.f;
    if (k < 64*C) v = kc[(size_t)k*64 + n];
    else if (k < 64*C + C) v = wd[(size_t)(k - 64*C)*64 + n];
    else if (k < 64*C + 2*C) v = wd[(size_t)(k - 64*C - C)*64 + n];
    __half h = __float2half_rn(v);
    BhT[e] = h;
    BlT[e] = __float2half_rn(v - __half2float(h));
}

// ---------------- fp16 MMA GEMM: C[M,64] = A[M,K] @ (Bh+Bl)[64,K]^T ----------------
// 128x64 CTA tile, 8 warps (warp = 32x32), KC=32 chunks double-buffered, splitK via grid.y.
__global__ __launch_bounds__(256) void gemm_mma(const __half* __restrict__ Ah,
                                                const __half* __restrict__ Bh,
                                                const __half* __restrict__ Bl,
                                                float* __restrict__ Cc, int M, int K){
    extern __shared__ __half sm[];
    const int RS = 40;
    const int OFF_BH = 128*RS;
    const int OFF_BL = 128*RS + 64*RS;
    const int BUFSZ  = 128*RS + 2*64*RS;
    int tid = threadIdx.x;
    int bm = blockIdx.x*128;
    int kLen = K / gridDim.y;
    int kBeg = blockIdx.y*kLen;
    int T = kLen >> 5;
    float* Cout = Cc + (size_t)blockIdx.y * M * 64;

    int arow = tid >> 1, ahalf = tid & 1;
    const __half* AG = Ah + (size_t)(bm+arow)*K + kBeg + ahalf*16;
    int brow = tid >> 2, bq = tid & 3;
    const __half* BhG = Bh + (size_t)brow*K + kBeg + bq*8;
    const __half* BlG = Bl + (size_t)brow*K + kBeg + bq*8;

    uint32_t sbase = smem_u32(sm);
    int wid = tid >> 5, lane = tid & 31;
    int wm = wid & 3, wn = wid >> 2;

    uint4 ra0, ra1, rbh, rbl;
    ra0 = *(const uint4*)(AG);     ra1 = *(const uint4*)(AG + 8);
    rbh = *(const uint4*)(BhG);    rbl = *(const uint4*)(BlG);
    {
        __half* buf = sm;
        *(uint4*)(buf + arow*RS + ahalf*16)     = ra0;
        *(uint4*)(buf + arow*RS + ahalf*16 + 8) = ra1;
        *(uint4*)(buf + OFF_BH + brow*RS + bq*8) = rbh;
        *(uint4*)(buf + OFF_BL + brow*RS + bq*8) = rbl;
    }
    __syncthreads();

    float acc[2][4][4];
#pragma unroll
    for (int mt=0;mt<2;mt++)
#pragma unroll
        for (int nt=0;nt<4;nt++)
#pragma unroll
            for (int q=0;q<4;q++) acc[mt][nt][q] = 0.f;

    for (int t = 0; t < T; t++){
        if (t+1 < T){
            ra0 = *(const uint4*)(AG + (size_t)(t+1)*32);
            ra1 = *(const uint4*)(AG + (size_t)(t+1)*32 + 8);
            rbh = *(const uint4*)(BhG + (size_t)(t+1)*32);
            rbl = *(const uint4*)(BlG + (size_t)(t+1)*32);
        }
        uint32_t bufo = (uint32_t)((t & 1) * BUFSZ) * 2;
#pragma unroll
        for (int ks = 0; ks < 2; ks++){
            int k0 = ks*16;
            uint32_t af[2][4];
#pragma unroll
            for (int mt=0;mt<2;mt++){
                int row = wm*32 + mt*16 + (lane & 15);
                int col = k0 + (lane >> 4)*8;
                uint32_t addr = sbase + bufo + (uint32_t)(row*RS + col)*2;
                ldsm_x4(af[mt][0], af[mt][1], af[mt][2], af[mt][3], addr);
            }
            uint32_t bfh[4][2], bfl[4][2];
#pragma unroll
            for (int nt=0;nt<4;nt++){
                int row = wn*32 + nt*8 + (lane & 7);
                int col = k0 + ((lane >> 3) & 1)*8;
                uint32_t addr = sbase + bufo + (uint32_t)(OFF_BH + row*RS + col)*2;
                ldsm_x2(bfh[nt][0], bfh[nt][1], addr);
                ldsm_x2(bfl[nt][0], bfl[nt][1], addr + (OFF_BL-OFF_BH)*2);
            }
#pragma unroll
            for (int mt=0;mt<2;mt++)
#pragma unroll
                for (int nt=0;nt<4;nt++){
                    mma_f16(acc[mt][nt], af[mt], bfh[nt]);
                    mma_f16(acc[mt][nt], af[mt], bfl[nt]);
                }
        }
        if (t+1 < T){
            __half* buf = sm + ((t+1) & 1) * BUFSZ;
            *(uint4*)(buf + arow*RS + ahalf*16)     = ra0;
            *(uint4*)(buf + arow*RS + ahalf*16 + 8) = ra1;
            *(uint4*)(buf + OFF_BH + brow*RS + bq*8) = rbh;
            *(uint4*)(buf + OFF_BL + brow*RS + bq*8) = rbl;
            __syncthreads();
        }
    }
#pragma unroll
    for (int mt=0;mt<2;mt++){
#pragma unroll
        for (int nt=0;nt<4;nt++){
            int r0 = bm + wm*32 + mt*16 + (lane >> 2);
            int c0 = wn*32 + nt*8 + (lane & 3)*2;
            if (r0 < M)     *(float2*)&Cout[(size_t)r0*64 + c0]     = make_float2(acc[mt][nt][0], acc[mt][nt][1]);
            if (r0+8 < M)   *(float2*)&Cout[(size_t)(r0+8)*64 + c0] = make_float2(acc[mt][nt][2], acc[mt][nt][3]);
        }
    }
}

// ---------------- fp32 GEMM N=32 (layer 0) ----------------
__global__ void gemm32(const float* __restrict__ A, const float* __restrict__ B,
                       float* __restrict__ Cc, int M, int N, int K){
    __shared__ float As[16][64];
    __shared__ float Bs[16][64];
    int tid = threadIdx.x;
    int bm = blockIdx.x * 64;
    int tm = tid >> 4, tn = tid & 15;
    float accv[4][4] = {};
    int arow = bm + (tid >> 2);
    int akq  = (tid & 3) * 4;
    int brow = tid >> 4;
    int bcol = (tid & 15) * 4;
    for (int k0 = 0; k0 < K; k0 += 16){
        float4 a4 = make_float4(0.f,0.f,0.f,0.f);
        if (arow < M) a4 = *(const float4*)(A + (size_t)arow*K + k0 + akq);
        float4 b4 = make_float4(0.f,0.f,0.f,0.f);
        if (bcol < N) b4 = *(const float4*)(B + (size_t)(k0+brow)*N + bcol);
        __syncthreads();
        int lr = tid >> 2;
        As[akq+0][lr] = a4.x; As[akq+1][lr] = a4.y; As[akq+2][lr] = a4.z; As[akq+3][lr] = a4.w;
        *(float4*)&Bs[brow][bcol] = b4;
        __syncthreads();
#pragma unroll
        for (int kk = 0; kk < 16; kk++){
            float4 av = *(const float4*)&As[kk][tm*4];
            float4 bv = *(const float4*)&Bs[kk][tn*4];
            float ar[4] = {av.x, av.y, av.z, av.w};
            float brr[4] = {bv.x, bv.y, bv.z, bv.w};
#pragma unroll
            for (int i=0;i<4;i++)
#pragma unroll
                for (int j=0;j<4;j++) accv[i][j] += ar[i]*brr[j];
        }
    }
#pragma unroll
    for (int i=0;i<4;i++){
        int r = bm + tm*4 + i;
        if (r >= M) continue;
#pragma unroll
        for (int j=0;j<4;j++){
            int c = tn*4 + j;
            if (c < N) Cc[(size_t)r*N + c] = accv[i][j];
        }
    }
}

// ---------------- fused layer-4 dot: out = A(fp16)[.., cellacc|hh|hl] @ [kc;wd;wd] + biases ----------------
__global__ void dotn_f16(const __half* __restrict__ Ah,
                         const float* __restrict__ kcB, const float* __restrict__ wdB,
                         const float* __restrict__ bc, const float* __restrict__ bd,
                         int C, float* __restrict__ out, int M, int Kp){
    extern __shared__ float sBv[];
    int tid = threadIdx.x;
    int Kc = 64*C, Kt = Kc + 2*C;
    for (int i = tid; i < Kc*3; i += blockDim.x) sBv[i] = kcB[i];
    for (int i = tid; i < C*3; i += blockDim.x){ sBv[Kc*3 + i] = wdB[i]; sBv[(Kc+C)*3 + i] = wdB[i]; }
    __syncthreads();
    int w = tid >> 5, lane = tid & 31;
    int r = blockIdx.x * 8 + w;
    if (r >= M) return;
    float a0=0.f, a1=0.f, a2=0.f;
    const __half* ap = Ah + (size_t)r*Kp;
    for (int k = lane*2; k < Kt; k += 64){
        __half2 h2 = *(const __half2*)(ap + k);
        float av0 = __half2float(h2.x);
        float av1 = __half2float(h2.y);
        a0 += av0 * sBv[k*3+0] + av1 * sBv[(k+1)*3+0];
        a1 += av0 * sBv[k*3+1] + av1 * sBv[(k+1)*3+1];
        a2 += av0 * sBv[k*3+2] + av1 * sBv[(k+1)*3+2];
    }
    for (int off=16; off; off>>=1){
        a0 += __shfl_down_sync(0xffffffffu, a0, off);
        a1 += __shfl_down_sync(0xffffffffu, a1, off);
        a2 += __shfl_down_sync(0xffffffffu, a2, off);
    }
    if (lane == 0){
        out[(size_t)r*3+0] = a0 + bc[0] + bd[0];
        out[(size_t)r*3+1] = a1 + bc[1] + bd[1];
        out[(size_t)r*3+2] = a2 + bc[2] + bd[2];
    }
}

// ---------------- elementwise ----------------
__global__ void combine0_kernel(const float* __restrict__ co, const float* __restrict__ cf,
                                const float* __restrict__ feat0,
                                const float* __restrict__ b0o, const float* __restrict__ b0f,
                                const float* __restrict__ wdf, const float* __restrict__ bdf,
                                float* __restrict__ out){
    int e = blockIdx.x*blockDim.x + threadIdx.x;
    if (e >= 9000*96) return;
    int row = e / 96, o = e - row*96;
    int n = row / 3;
    float v;
    if (o < 32) v = co[n*32+o] + b0o[o];
    else if (o < 64) v = cf[(size_t)row*32 + (o-32)] + b0f[o-32];
    else {
        int oo = o - 64;
        v = bdf[oo];
        for (int c=0;c<3;c++) v += feat0[row*3+c]*wdf[c*32+oo];
    }
    out[e] = v;
}

__global__ void combine_kernel(const float* __restrict__ oc, int nsplit,
                               const float* __restrict__ bc, const float* __restrict__ bd,
                               const float* __restrict__ prev, float* __restrict__ out, int C){
    int e = blockIdx.x*blockDim.x + threadIdx.x;
    if (e >= 9000*C) return;
    int o = e % C;
    float v = bc[o] + bd[o];
    for (int j = 0; j < nsplit; j++) v += oc[(size_t)j*9000*64 + e];
    if (prev) v += prev[e];
    out[e] = v;
}

__global__ void final_kernel(const float* __restrict__ out4, const float* __restrict__ p1,
                             const float* __restrict__ p0, float* __restrict__ dout){
    int e = blockIdx.x*blockDim.x + threadIdx.x;
    if (e >= NF*3) return;
    int n = e/3, d = e - n*3;
    float pc0 = out4[(n*3+0)*3+d] * 0.25f * (1.0f/16.0f);
    float pc1 = out4[(n*3+1)*3+d] * 0.25f;
    float pc2 = out4[(n*3+2)*3+d] * 0.25f;
    float p_c = p1[e] + pc0;
    dout[e] = p_c;
    dout[9000 + e] = (p_c - p0[e]) / 0.1f;
    dout[18000 + n*6 + d]     = pc1;
    dout[18000 + n*6 + 3 + d] = pc2;
}

// ---------------- launch ----------------
extern "C" void kernel_launch(void* const* d_in, const int* in_sizes, int n_in,
                              void* d_out, int out_size){
    const float* v0e  = (const float*)d_in[1];
    const float* p0   = (const float*)d_in[2];
    const float* v0   = (const float*)d_in[3];
    const float* a    = (const float*)d_in[4];
    const float* other= (const float*)d_in[5];
    const float* box  = (const float*)d_in[6];
    const float* boxf = (const float*)d_in[7];
    const float* bmask= (const float*)d_in[9];
    const float* k0f  = (const float*)d_in[10];
    const float* b0f  = (const float*)d_in[11];
    const float* k0o  = (const float*)d_in[12];
    const float* b0o  = (const float*)d_in[13];
    const float* wdf  = (const float*)d_in[14];
    const float* bdf  = (const float*)d_in[15];
    const float *kc[4], *bcp[4], *wd[4], *bdp[4];
    if (in_sizes[18] == 262144){
        for (int i=0;i<4;i++){
            kc[i]=(const float*)d_in[16+2*i]; bcp[i]=(const float*)d_in[17+2*i];
            wd[i]=(const float*)d_in[24+2*i]; bdp[i]=(const float*)d_in[25+2*i];
        }
    } else {
        for (int i=0;i<4;i++){
            kc[i]=(const float*)d_in[16+4*i]; bcp[i]=(const float*)d_in[17+4*i];
            wd[i]=(const float*)d_in[18+4*i]; bdp[i]=(const float*)d_in[19+4*i];
        }
    }
    float* dout = (float*)d_out;

    float *p1, *feat0, *A0, *Abox, *cfb, *cob, *ocb, *o1, *o2, *fw8, *bw8;
    __half *Ahp, *Bhp, *Blp;
    int *fcnt, *fidx, *fbase, *bcnt, *bidx, *bbase;
    cudaGetSymbolAddress((void**)&p1, g_p1);
    cudaGetSymbolAddress((void**)&feat0, g_feat0);
    cudaGetSymbolAddress((void**)&A0, g_A0);
    cudaGetSymbolAddress((void**)&Abox, g_Abox);
    cudaGetSymbolAddress((void**)&Ahp, g_Ah);
    cudaGetSymbolAddress((void**)&Bhp, g_Bh);
    cudaGetSymbolAddress((void**)&Blp, g_Bl);
    cudaGetSymbolAddress((void**)&cfb, g_cf);
    cudaGetSymbolAddress((void**)&cob, g_co);
    cudaGetSymbolAddress((void**)&ocb, g_oc);
    cudaGetSymbolAddress((void**)&o1, g_out1);
    cudaGetSymbolAddress((void**)&o2, g_out2);
    cudaGetSymbolAddress((void**)&fw8, g_fw8);
    cudaGetSymbolAddress((void**)&bw8, g_bw8);
    cudaGetSymbolAddress((void**)&fcnt, g_fcnt);
    cudaGetSymbolAddress((void**)&fidx, g_fidx);
    cudaGetSymbolAddress((void**)&fbase, g_fbase);
    cudaGetSymbolAddress((void**)&bcnt, g_bcnt);
    cudaGetSymbolAddress((void**)&bidx, g_bidx);
    cudaGetSymbolAddress((void**)&bbase, g_bbase);

    cudaFuncSetAttribute(scatter_big, cudaFuncAttributeMaxDynamicSharedMemorySize, 80000);
    cudaFuncSetAttribute(gemm_mma,    cudaFuncAttributeMaxDynamicSharedMemorySize, 41000);
    cudaFuncSetAttribute(dotn_f16,    cudaFuncAttributeMaxDynamicSharedMemorySize, 52000);

    // Kp = 64*C + 2*C (multiple of 64): layer0 C=96 -> 6336; layers 1-3 C=64 -> 4224
    int Kp[4]       = {6336, 4224, 4224, 4224};
    size_t BOff[3]  = {0, (size_t)64*6336, (size_t)64*6336 + (size_t)64*4224};
    int Cin[4]      = {96, 64, 64, 64};

    // weight-only conversions first (off the data-dependent chain)
    convB<<<(64*6336+255)/256, 256>>>(kc[0], wd[0], 96, 6336, Bhp + BOff[0], Blp + BOff[0]);
    convB<<<(64*4224+255)/256, 256>>>(kc[1], wd[1], 64, 4224, Bhp + BOff[1], Blp + BOff[1]);
    convB<<<(64*4224+255)/256, 256>>>(kc[2], wd[2], 64, 4224, Bhp + BOff[2], Blp + BOff[2]);

    prep_kernel<<<(NF+127)/128, 128>>>(p0, v0, a, other, v0e, p1, feat0, dout + 36000);
    neigh_kernel<<<NF, 256>>>(p1, NF, p1, nullptr, 1, fcnt, fidx, fbase, fw8);
    neigh_kernel<<<NF, 256>>>(box, NB, p1, bmask, 0, bcnt, bidx, bbase, bw8);

    // layer 0
    scatter9<<<NF, 96>>>(feat0, fcnt, fidx, fbase, fw8, A0);
    gemm32<<<(9000+63)/64, 256>>>(A0, k0f, cfb, 9000, 32, 192);
    scatter1<<<NF/8, 64>>>(boxf, bcnt, bidx, bbase, bw8, Abox);
    gemm32<<<(3000+63)/64, 256>>>(Abox, k0o, cob, 3000, 32, 64);
    combine0_kernel<<<(9000*96+255)/256, 256>>>(cob, cfb, feat0, b0o, b0f, wdf, bdf, o1);

    float* cur = o1; float* nxt = o2;
    for (int i=0;i<4;i++){
        int ci = Cin[i];
        int F = 3*ci, F4 = F/4;
        int bD = ((F4 + 31)/32)*32;
        scatter_big<<<NF, bD, (size_t)64*F*4>>>(cur, F, ci, fcnt, fidx, fbase, fw8, Ahp, Kp[i]);
        if (i < 3){
            gemm_mma<<<dim3(71,2), 256, 40960>>>(Ahp, Bhp + BOff[i], Blp + BOff[i], ocb, 9000, Kp[i]);
            combine_kernel<<<(9000*64+255)/256, 256>>>(ocb, 2,
                bcp[i], bdp[i], (i==1||i==2) ? cur : nullptr, nxt, 64);
        } else {
            dotn_f16<<<(9000+7)/8, 256, (size_t)4224*3*4>>>(Ahp, kc[3], wd[3],
                bcp[3], bdp[3], 64, nxt, 9000, Kp[3]);
        }
        float* t = cur; cur = nxt; nxt = t;
    }
    final_kernel<<<(NF*3+255)/256, 256>>>(cur, p1, p0, dout);
}

// round 16
// speedup vs baseline: 1.2357x; 1.1085x over previous
#include <cuda_runtime.h>
#include <cuda_fp16.h>
#include <math.h>
#include <stdint.h>

#define NF 3000
#define NB 1500
#define RAD2 9.0f
#define INV_R (1.0f/3.0f)
#define CAP 256
#define EPSF 1e-8f
#define FOUR_OVER_PI 1.2732395447351628f

// ---------------- static device scratch ----------------
__device__ float g_p1[NF*3];
__device__ float g_feat0[NF*9];
__device__ int   g_fcnt[NF];
__device__ int   g_fidx[NF*64];
__device__ int   g_fbase[NF*64];
__device__ float g_fw8[NF*512];
__device__ int   g_bcnt[NF];
__device__ int   g_bidx[NF*64];
__device__ int   g_bbase[NF*64];
__device__ float g_bw8[NF*512];
__device__ float g_A0[9000*192];
__device__ float g_Abox[NF*64];
__device__ __half g_Ah[(size_t)9088*6400];
__device__ __half g_Bh[64*14848];
__device__ __half g_Bl[64*14848];
__device__ float g_oc[4*9000*64];
__device__ float g_out1[9000*96];
__device__ float g_out2[9000*96];

// ---------------- helpers ----------------
__device__ __forceinline__ uint32_t smem_u32(const void* p){
    uint32_t a;
    asm("{ .reg .u64 t; cvta.to.shared.u64 t, %1; cvt.u32.u64 %0, t; }" : "=r"(a) : "l"(p));
    return a;
}
__device__ __forceinline__ void ldsm_x4(uint32_t& r0, uint32_t& r1, uint32_t& r2, uint32_t& r3, uint32_t addr){
    asm volatile("ldmatrix.sync.aligned.m8n8.x4.shared.b16 {%0,%1,%2,%3}, [%4];"
        : "=r"(r0), "=r"(r1), "=r"(r2), "=r"(r3) : "r"(addr));
}
__device__ __forceinline__ void ldsm_x2(uint32_t& r0, uint32_t& r1, uint32_t addr){
    asm volatile("ldmatrix.sync.aligned.m8n8.x2.shared.b16 {%0,%1}, [%2];"
        : "=r"(r0), "=r"(r1) : "r"(addr));
}
__device__ __forceinline__ void mma_f16(float* c, const uint32_t* a, const uint32_t* b){
    asm volatile("mma.sync.aligned.m16n8k16.row.col.f32.f16.f16.f32 "
        "{%0,%1,%2,%3}, {%4,%5,%6,%7}, {%8,%9}, {%0,%1,%2,%3};"
        : "+f"(c[0]), "+f"(c[1]), "+f"(c[2]), "+f"(c[3])
        : "r"(a[0]), "r"(a[1]), "r"(a[2]), "r"(a[3]), "r"(b[0]), "r"(b[1]));
}

// ---------------- geometry ----------------
__device__ __forceinline__ float sgnf(float v){ return (v>0.f)?1.f:((v<0.f)?-1.f:0.f); }

__device__ __forceinline__ void ball_to_cube(float x,float y,float z,float&obx,float&oby,float&obz){
    float sq = x*x+y*y+z*z;
    float norm = sqrtf(fmaxf(sq,EPSF));
    float xy_sq = x*x+y*y;
    bool polar = (1.25f*z*z) > xy_sq;
    float s_p = sqrtf(3.0f*norm/(norm+fabsf(z)+EPSF));
    float s_e = norm / sqrtf(fmaxf(xy_sq,EPSF));
    float cx = polar ? x*s_p : x*s_e;
    float cy = polar ? y*s_p : y*s_e;
    float cz = polar ? sgnf(z)*norm : 1.5f*z;
    float nxy = sqrtf(fmaxf(cx*cx+cy*cy,EPSF));
    bool xdom = fabsf(cy) <= fabsf(cx);
    float sx = (fabsf(cx) > EPSF) ? cx : 1.0f;
    float sy = (fabsf(cy) > EPSF) ? cy : 1.0f;
    float bx1 = sgnf(cx)*nxy;
    float by1 = bx1*FOUR_OVER_PI*atanf(cy/sx);
    float by2 = sgnf(cy)*nxy;
    float bx2 = by2*FOUR_OVER_PI*atanf(cx/sy);
    float bx = xdom ? bx1 : bx2;
    float by = xdom ? by1 : by2;
    if (cx*cx+cy*cy < EPSF){ bx=0.f; by=0.f; }
    if (sq < EPSF){ bx=0.f; by=0.f; cz=0.f; }
    obx=bx; oby=by; obz=cz;
}

// ---------------- prep ----------------
__global__ void prep_kernel(const float* __restrict__ p0,const float* __restrict__ v0,
                            const float* __restrict__ a,const float* __restrict__ other,
                            const float* __restrict__ v0e,
                            float* __restrict__ p1,float* __restrict__ feat0,
                            float* __restrict__ outState){
    int i = blockIdx.x*blockDim.x + threadIdx.x;
    if (i >= NF) return;
#pragma unroll
    for (int d=0; d<3; d++){
        float vv0 = v0[i*3+d];
        float v1  = vv0 + 0.1f*a[i*3+d];
        float pp1 = p0[i*3+d] + 0.1f*(vv0+v1)*0.5f;
        p1[i*3+d]        = pp1;
        feat0[i*9+d]     = v1;
        feat0[i*9+3+d]   = other[i*3+d];
        feat0[i*9+6+d]   = v0e[i*3+d];
        outState[i*3+d]  = v0e[i*3+d];
    }
}

// ---------------- neighbor search ----------------
__global__ void neigh_kernel(const float* __restrict__ pin, int Mp,
                             const float* __restrict__ pout,
                             const float* __restrict__ mask, int selfEx,
                             int* __restrict__ cntO, int* __restrict__ idxO,
                             int* __restrict__ baseO, float* __restrict__ w8O){
    __shared__ float cd2[CAP];
    __shared__ int   cid[CAP];
    __shared__ unsigned long long keys[CAP];
    __shared__ int scnt;
    __shared__ int   sM[64];
    __shared__ int   sB[64];
    __shared__ float sW8[64*8];
    __shared__ unsigned skey[64];
    int n = blockIdx.x, tid = threadIdx.x;
    float qx = pout[n*3], qy = pout[n*3+1], qz = pout[n*3+2];
    if (tid==0) scnt = 0;
    __syncthreads();
    for (int m = tid; m < Mp; m += blockDim.x){
        if (selfEx && m==n) continue;
        if (mask && !(mask[m] > 0.f)) continue;
        float dx = pin[m*3]-qx, dy = pin[m*3+1]-qy, dz = pin[m*3+2]-qz;
        float d2 = dx*dx + dy*dy + dz*dz;
        if (d2 <= RAD2){
            int p = atomicAdd(&scnt, 1);
            if (p < CAP){ cd2[p]=d2; cid[p]=m; }
        }
    }
    __syncthreads();
    int cn = min(scnt, CAP);
    for (int t = tid; t < CAP; t += blockDim.x)
        keys[t] = (t < cn) ? ((((unsigned long long)__float_as_uint(cd2[t]))<<32) | (unsigned)cid[t])
                           : 0xFFFFFFFFFFFFFFFFull;
    __syncthreads();
    for (int k = 2; k <= CAP; k <<= 1){
        for (int j = k>>1; j > 0; j >>= 1){
            if (tid < 128){
                int i = ((tid & ~(j-1)) << 1) | (tid & (j-1));
                int ixj = i | j;
                bool asc = ((i & k) == 0);
                unsigned long long av = keys[i], bv = keys[ixj];
                if ((av > bv) == asc){ keys[i]=bv; keys[ixj]=av; }
            }
            __syncthreads();
        }
    }
    int keep = min(cn, 64);
    if (tid==0) cntO[n] = keep;
    for (int t = tid; t < keep; t += blockDim.x){
        unsigned long long key = keys[t];
        int m = (int)(key & 0xFFFFFFFFull);
        float dx = pin[m*3]-qx, dy = pin[m*3+1]-qy, dz = pin[m*3+2]-qz;
        float ux = dx*INV_R, uy = dy*INV_R, uz = dz*INV_R;
        float r2 = ux*ux + uy*uy + uz*uz;
        float t1 = 1.f - r2;
        float win = fminf(fmaxf(t1*t1*t1, 0.f), 1.f);
        float bx, by, bz;
        ball_to_cube(ux, uy, uz, bx, by, bz);
        float cxx = fminf(fmaxf((bx*0.5f+0.5f)*3.f, 0.f), 3.f);
        float cyy = fminf(fmaxf((by*0.5f+0.5f)*3.f, 0.f), 3.f);
        float czz = fminf(fmaxf((bz*0.5f+0.5f)*3.f, 0.f), 3.f);
        int c0x = min((int)floorf(cxx), 2);
        int c0y = min((int)floorf(cyy), 2);
        int c0z = min((int)floorf(czz), 2);
        float fx = cxx - (float)c0x, fy = cyy - (float)c0y, fz = czz - (float)c0z;
        sM[t] = m;
        sB[t] = (c0x*4 + c0y)*4 + c0z;
        float gx[2] = {1.f-fx, fx}, gy[2] = {1.f-fy, fy}, gz[2] = {1.f-fz, fz};
        int jj = 0;
        for (int i2=0;i2<2;i2++) for (int j2=0;j2<2;j2++) for (int l2=0;l2<2;l2++)
            sW8[t*8 + (jj++)] = gx[i2]*gy[j2]*gz[l2]*win;
    }
    for (int t = tid; t < 64; t += blockDim.x)
        skey[t] = (t < keep) ? (unsigned)((sB[t] << 6) | t) : 0xFFFFFFFFu;
    __syncthreads();
    for (int k = 2; k <= 64; k <<= 1){
        for (int j = k>>1; j > 0; j >>= 1){
            if (tid < 32){
                int i = ((tid & ~(j-1)) << 1) | (tid & (j-1));
                int ixj = i | j;
                bool asc = ((i & k) == 0);
                unsigned av = skey[i], bv = skey[ixj];
                if ((av > bv) == asc){ skey[i]=bv; skey[ixj]=av; }
            }
            __syncthreads();
        }
    }
    for (int t = tid; t < keep; t += blockDim.x){
        int s = (int)(skey[t] & 63u);
        idxO[n*64+t]  = sM[s];
        baseO[n*64+t] = sB[s];
#pragma unroll
        for (int j=0;j<8;j++) w8O[n*512 + t*8 + j] = sW8[s*8 + j];
    }
}

__constant__ int c_coff[8] = {0,1,4,5,16,17,20,21};

// ---------------- scatter layer0 fluid (F=9) ----------------
__global__ void scatter9(const float* __restrict__ feats,
                         const int* __restrict__ cnt, const int* __restrict__ nidx,
                         const int* __restrict__ nbase, const float* __restrict__ nw8,
                         float* __restrict__ A){
    __shared__ float planes[8*576];
    __shared__ float sfeat[64*9];
    __shared__ float sW[512];
    __shared__ int   sBase[64];
    __shared__ int   sIdx[64];
    int n = blockIdx.x, tid = threadIdx.x;
    int cn = cnt[n];
    for (int e = tid; e < 8*576; e += 96) planes[e] = 0.f;
    if (tid < cn){ sIdx[tid] = nidx[n*64+tid]; sBase[tid] = nbase[n*64+tid]; }
    for (int e = tid; e < cn*8; e += 96) sW[e] = nw8[n*512+e];
    __syncthreads();
    for (int e = tid; e < cn*9; e += 96){
        int k = e/9, f = e-k*9;
        sfeat[e] = feats[(size_t)sIdx[k]*9 + f];
    }
    __syncthreads();
    if (tid < 72){
        int j = tid/9, f = tid - j*9;
        int off = c_coff[j];
        float r = 0.f; int prevb = -1;
        for (int k = 0; k < cn; k++){
            int b = sBase[k];
            if (b != prevb){
                if (prevb >= 0) planes[j*576 + (prevb+off)*9 + f] += r;
                prevb = b; r = 0.f;
            }
            r += sW[k*8+j]*sfeat[k*9+f];
        }
        if (prevb >= 0) planes[j*576 + (prevb+off)*9 + f] += r;
    }
    __syncthreads();
    for (int e = tid; e < 576; e += 96){
        int l = e/9, f = e-l*9;
        int s = f/3, c = f-s*3;
        float v = 0.f;
#pragma unroll
        for (int j=0;j<8;j++) v += planes[j*576+e];
        A[(size_t)(n*3+s)*192 + l*3 + c] = v;
    }
}

// ---------------- scatter box (F=1) ----------------
__global__ void scatter1(const float* __restrict__ feats,
                         const int* __restrict__ cnt, const int* __restrict__ nidx,
                         const int* __restrict__ nbase, const float* __restrict__ nw8,
                         float* __restrict__ A){
    __shared__ float planes[8*8*64];
    __shared__ float sF[8*64];
    __shared__ float sW[8*512];
    __shared__ int   sBase[8*64];
    __shared__ int   sCn[8];
    int tid = threadIdx.x, nb = blockIdx.x;
    for (int e = tid; e < 8*8*64; e += 64) planes[e] = 0.f;
    for (int e = tid; e < 8*64; e += 64){
        int q = e>>6, k = e&63;
        int n = nb*8+q;
        if (k==0) sCn[q] = cnt[n];
        int cnq = cnt[n];
        if (k < cnq){ sBase[e] = nbase[n*64+k]; sF[e] = feats[nidx[n*64+k]]; }
    }
    for (int e = tid; e < 8*512; e += 64){
        int q = e>>9, r = e&511;
        sW[e] = nw8[(size_t)(nb*8+q)*512 + r];
    }
    __syncthreads();
    {
        int q = tid>>3, j = tid&7;
        int off = c_coff[j];
        int cnq = sCn[q];
        float r = 0.f; int prevb = -1;
        for (int k = 0; k < cnq; k++){
            int b = sBase[q*64+k];
            if (b != prevb){
                if (prevb >= 0) planes[(q*8+j)*64 + prevb+off] += r;
                prevb = b; r = 0.f;
            }
            r += sW[q*512 + k*8 + j]*sF[q*64+k];
        }
        if (prevb >= 0) planes[(q*8+j)*64 + prevb+off] += r;
    }
    __syncthreads();
    for (int e = tid; e < 512; e += 64){
        int q = e>>6, l = e&63;
        float v = 0.f;
#pragma unroll
        for (int j=0;j<8;j++) v += planes[(q*8+j)*64 + l];
        A[(size_t)(nb*8+q)*64 + l] = v;
    }
}

// ---------------- scatter (big): batched prefetch; A rows [cellacc | hh | hl | zero-pad] ----------------
__global__ void scatter_big(const float* __restrict__ feats, int F, int C,
                            const int* __restrict__ cnt, const int* __restrict__ nidx,
                            const int* __restrict__ nbase, const float* __restrict__ nw8,
                            __half* __restrict__ Ah, int Kp){
    extern __shared__ float acc[];
    __shared__ int sIdx[64]; __shared__ int sBase[64]; __shared__ float sW[512];
    float4* acc4 = (float4*)acc;
    int n = blockIdx.x, tid = threadIdx.x, bd = blockDim.x;
    int F4 = F >> 2;
    int cn = cnt[n];
    for (int e = tid; e < 64*F4; e += bd) acc4[e] = make_float4(0.f,0.f,0.f,0.f);
    for (int e = tid; e < cn; e += bd){ sIdx[e] = nidx[n*64+e]; sBase[e] = nbase[n*64+e]; }
    for (int e = tid; e < cn*8; e += bd) sW[e] = nw8[n*512+e];
    __syncthreads();
    int f4 = tid;
    if (f4 < F4){
        float4 r[8];
        int prevb = -1;
#pragma unroll
        for (int j=0;j<8;j++) r[j] = make_float4(0.f,0.f,0.f,0.f);
        for (int k0 = 0; k0 < cn; k0 += 8){
            int kb = min(8, cn - k0);
            float4 fv[8];
#pragma unroll
            for (int j=0;j<8;j++){
                if (j < kb){
                    float4 t = ((const float4*)(feats + (size_t)sIdx[k0+j]*F))[f4];
                    t.x = fmaxf(t.x,0.f); t.y = fmaxf(t.y,0.f);
                    t.z = fmaxf(t.z,0.f); t.w = fmaxf(t.w,0.f);
                    fv[j] = t;
                }
            }
#pragma unroll
            for (int j=0;j<8;j++){
                if (j < kb){
                    int b = sBase[k0+j];
                    if (b != prevb){
                        if (prevb >= 0){
#pragma unroll
                            for (int q=0;q<8;q++){
                                int ai = (prevb + c_coff[q])*F4 + f4;
                                float4 t = acc4[ai];
                                t.x += r[q].x; t.y += r[q].y; t.z += r[q].z; t.w += r[q].w;
                                acc4[ai] = t;
                            }
                        }
                        prevb = b;
#pragma unroll
                        for (int q=0;q<8;q++) r[q] = make_float4(0.f,0.f,0.f,0.f);
                    }
#pragma unroll
                    for (int q=0;q<8;q++){
                        float w = sW[(k0+j)*8+q];
                        r[q].x += w*fv[j].x; r[q].y += w*fv[j].y;
                        r[q].z += w*fv[j].z; r[q].w += w*fv[j].w;
                    }
                }
            }
        }
        if (prevb >= 0){
#pragma unroll
            for (int q=0;q<8;q++){
                int ai = (prevb + c_coff[q])*F4 + f4;
                float4 t = acc4[ai];
                t.x += r[q].x; t.y += r[q].y; t.z += r[q].z; t.w += r[q].w;
                acc4[ai] = t;
            }
        }
    }
    __syncthreads();
    for (int e4 = tid; e4 < 64*F4; e4 += bd){
        int l = e4 / F4, fl = e4 - l*F4;
        int f = fl*4;
        int s = f / C, c = f - s*C;
        float4 v = acc4[e4];
        size_t base = (size_t)(n*3+s)*Kp + l*C + c;
        *(__half2*)(Ah+base)   = __floats2half2_rn(v.x, v.y);
        *(__half2*)(Ah+base+2) = __floats2half2_rn(v.z, v.w);
    }
    for (int e = tid; e < 3*C; e += bd){
        int s = e / C, c = e - s*C;
        float v = fmaxf(feats[(size_t)n*F + s*C + c], 0.f);
        __half hh = __float2half_rn(v);
        float lo = v - __half2float(hh);
        Ah[(size_t)(n*3+s)*Kp + 64*C + c]     = hh;
        Ah[(size_t)(n*3+s)*Kp + 64*C + C + c] = __float2half_rn(lo);
    }
    // zero-fill K padding (layer 0: columns 66C..Kp)
    int kt = 66*C;
    int pad = Kp - kt;
    if (pad > 0){
        for (int e = tid; e < 3*pad; e += bd){
            int s = e / pad, c = e - s*pad;
            Ah[(size_t)(n*3+s)*Kp + kt + c] = __float2half_rn(0.f);
        }
    }
}

// ---------------- B' conversion (all 3 MMA layers in one launch) ----------------
__global__ void convB3(const float* __restrict__ kc0, const float* __restrict__ wd0,
                       const float* __restrict__ kc1, const float* __restrict__ wd1,
                       const float* __restrict__ kc2, const float* __restrict__ wd2,
                       __half* __restrict__ Bh, __half* __restrict__ Bl){
    int layer = blockIdx.y;
    int C  = (layer==0) ? 96 : 64;
    int Kp = (layer==0) ? 6400 : 4224;
    size_t off = (layer==0) ? 0 : ((layer==1) ? (size_t)64*6400 : (size_t)64*6400 + (size_t)64*4224);
    const float* kc = (layer==0) ? kc0 : ((layer==1) ? kc1 : kc2);
    const float* wd = (layer==0) ? wd0 : ((layer==1) ? wd1 : wd2);
    int e = blockIdx.x*blockDim.x + threadIdx.x;
    if (e >= 64*Kp) return;
    int n = e / Kp, k = e - n*Kp;
    float v = 0.f;
    if (k < 64*C) v = kc[(size_t)k*64 + n];
    else if (k < 64*C + C) v = wd[(size_t)(k - 64*C)*64 + n];
    else if (k < 64*C + 2*C) v = wd[(size_t)(k - 64*C - C)*64 + n];
    __half h = __float2half_rn(v);
    Bh[off + e] = h;
    Bl[off + e] = __float2half_rn(v - __half2float(h));
}

// ---------------- fp16 MMA GEMM: C[M,64] = A[M,K] @ (Bh+Bl)[64,K]^T, splitK via grid.y ----------------
__global__ __launch_bounds__(256) void gemm_mma(const __half* __restrict__ Ah,
                                                const __half* __restrict__ Bh,
                                                const __half* __restrict__ Bl,
                                                float* __restrict__ Cc, int M, int K){
    extern __shared__ __half sm[];
    const int RS = 40;
    const int OFF_BH = 128*RS;
    const int OFF_BL = 128*RS + 64*RS;
    const int BUFSZ  = 128*RS + 2*64*RS;
    int tid = threadIdx.x;
    int bm = blockIdx.x*128;
    int kLen = K / gridDim.y;
    int kBeg = blockIdx.y*kLen;
    int T = kLen >> 5;
    float* Cout = Cc + (size_t)blockIdx.y * M * 64;

    int arow = tid >> 1, ahalf = tid & 1;
    const __half* AG = Ah + (size_t)(bm+arow)*K + kBeg + ahalf*16;
    int brow = tid >> 2, bq = tid & 3;
    const __half* BhG = Bh + (size_t)brow*K + kBeg + bq*8;
    const __half* BlG = Bl + (size_t)brow*K + kBeg + bq*8;

    uint32_t sbase = smem_u32(sm);
    int wid = tid >> 5, lane = tid & 31;
    int wm = wid & 3, wn = wid >> 2;

    uint4 ra0, ra1, rbh, rbl;
    ra0 = *(const uint4*)(AG);     ra1 = *(const uint4*)(AG + 8);
    rbh = *(const uint4*)(BhG);    rbl = *(const uint4*)(BlG);
    {
        __half* buf = sm;
        *(uint4*)(buf + arow*RS + ahalf*16)     = ra0;
        *(uint4*)(buf + arow*RS + ahalf*16 + 8) = ra1;
        *(uint4*)(buf + OFF_BH + brow*RS + bq*8) = rbh;
        *(uint4*)(buf + OFF_BL + brow*RS + bq*8) = rbl;
    }
    __syncthreads();

    float acc[2][4][4];
#pragma unroll
    for (int mt=0;mt<2;mt++)
#pragma unroll
        for (int nt=0;nt<4;nt++)
#pragma unroll
            for (int q=0;q<4;q++) acc[mt][nt][q] = 0.f;

    for (int t = 0; t < T; t++){
        if (t+1 < T){
            ra0 = *(const uint4*)(AG + (size_t)(t+1)*32);
            ra1 = *(const uint4*)(AG + (size_t)(t+1)*32 + 8);
            rbh = *(const uint4*)(BhG + (size_t)(t+1)*32);
            rbl = *(const uint4*)(BlG + (size_t)(t+1)*32);
        }
        uint32_t bufo = (uint32_t)((t & 1) * BUFSZ) * 2;
#pragma unroll
        for (int ks = 0; ks < 2; ks++){
            int k0 = ks*16;
            uint32_t af[2][4];
#pragma unroll
            for (int mt=0;mt<2;mt++){
                int row = wm*32 + mt*16 + (lane & 15);
                int col = k0 + (lane >> 4)*8;
                uint32_t addr = sbase + bufo + (uint32_t)(row*RS + col)*2;
                ldsm_x4(af[mt][0], af[mt][1], af[mt][2], af[mt][3], addr);
            }
            uint32_t bfh[4][2], bfl[4][2];
#pragma unroll
            for (int nt=0;nt<4;nt++){
                int row = wn*32 + nt*8 + (lane & 7);
                int col = k0 + ((lane >> 3) & 1)*8;
                uint32_t addr = sbase + bufo + (uint32_t)(OFF_BH + row*RS + col)*2;
                ldsm_x2(bfh[nt][0], bfh[nt][1], addr);
                ldsm_x2(bfl[nt][0], bfl[nt][1], addr + (OFF_BL-OFF_BH)*2);
            }
#pragma unroll
            for (int mt=0;mt<2;mt++)
#pragma unroll
                for (int nt=0;nt<4;nt++){
                    mma_f16(acc[mt][nt], af[mt], bfh[nt]);
                    mma_f16(acc[mt][nt], af[mt], bfl[nt]);
                }
        }
        if (t+1 < T){
            __half* buf = sm + ((t+1) & 1) * BUFSZ;
            *(uint4*)(buf + arow*RS + ahalf*16)     = ra0;
            *(uint4*)(buf + arow*RS + ahalf*16 + 8) = ra1;
            *(uint4*)(buf + OFF_BH + brow*RS + bq*8) = rbh;
            *(uint4*)(buf + OFF_BL + brow*RS + bq*8) = rbl;
            __syncthreads();
        }
    }
#pragma unroll
    for (int mt=0;mt<2;mt++){
#pragma unroll
        for (int nt=0;nt<4;nt++){
            int r0 = bm + wm*32 + mt*16 + (lane >> 2);
            int c0 = wn*32 + nt*8 + (lane & 3)*2;
            if (r0 < M)     *(float2*)&Cout[(size_t)r0*64 + c0]     = make_float2(acc[mt][nt][0], acc[mt][nt][1]);
            if (r0+8 < M)   *(float2*)&Cout[(size_t)(r0+8)*64 + c0] = make_float2(acc[mt][nt][2], acc[mt][nt][3]);
        }
    }
}

// ---------------- layer-0 GEMMs (fluid + box) with fused epilogues -> o1 ----------------
__global__ void l0gemm(const float* __restrict__ A0, const float* __restrict__ k0f,
                       const float* __restrict__ b0f, const float* __restrict__ feat0,
                       const float* __restrict__ wdf, const float* __restrict__ bdf,
                       const float* __restrict__ Abox, const float* __restrict__ k0o,
                       const float* __restrict__ b0o, float* __restrict__ o1){
    __shared__ float As[16][64];
    __shared__ float Bs[16][64];
    int tid = threadIdx.x;
    bool fluid = blockIdx.x < 141;
    const float* A = fluid ? A0 : Abox;
    const float* B = fluid ? k0f : k0o;
    int M = fluid ? 9000 : 3000;
    int K = fluid ? 192 : 64;
    int bm = (fluid ? blockIdx.x : (blockIdx.x - 141)) * 64;
    int tm = tid >> 4, tn = tid & 15;
    float accv[4][4] = {};
    int arow = bm + (tid >> 2);
    int akq  = (tid & 3) * 4;
    int brow = tid >> 4;
    int bcol = (tid & 15) * 4;
    for (int k0 = 0; k0 < K; k0 += 16){
        float4 a4 = make_float4(0.f,0.f,0.f,0.f);
        if (arow < M) a4 = *(const float4*)(A + (size_t)arow*K + k0 + akq);
        float4 b4 = make_float4(0.f,0.f,0.f,0.f);
        if (bcol < 32) b4 = *(const float4*)(B + (size_t)(k0+brow)*32 + bcol);
        __syncthreads();
        int lr = tid >> 2;
        As[akq+0][lr] = a4.x; As[akq+1][lr] = a4.y; As[akq+2][lr] = a4.z; As[akq+3][lr] = a4.w;
        *(float4*)&Bs[brow][bcol] = b4;
        __syncthreads();
#pragma unroll
        for (int kk = 0; kk < 16; kk++){
            float4 av = *(const float4*)&As[kk][tm*4];
            float4 bv = *(const float4*)&Bs[kk][tn*4];
            float ar[4] = {av.x, av.y, av.z, av.w};
            float brr[4] = {bv.x, bv.y, bv.z, bv.w};
#pragma unroll
            for (int i=0;i<4;i++)
#pragma unroll
                for (int j=0;j<4;j++) accv[i][j] += ar[i]*brr[j];
        }
    }
#pragma unroll
    for (int i=0;i<4;i++){
        int r = bm + tm*4 + i;
        if (r >= M) continue;
        float f0=0.f, f1=0.f, f2=0.f;
        if (fluid){
            f0 = feat0[r*3+0]; f1 = feat0[r*3+1]; f2 = feat0[r*3+2];
        }
#pragma unroll
        for (int j=0;j<4;j++){
            int c = tn*4 + j;
            if (c >= 32) continue;
            if (fluid){
                o1[(size_t)r*96 + 32 + c] = accv[i][j] + b0f[c];
                o1[(size_t)r*96 + 64 + c] = bdf[c] + f0*wdf[c] + f1*wdf[32+c] + f2*wdf[64+c];
            } else {
                float v = accv[i][j] + b0o[c];
#pragma unroll
                for (int s=0;s<3;s++) o1[(size_t)(r*3+s)*96 + c] = v;
            }
        }
    }
}

// ---------------- fused layer-4 dot ----------------
__global__ void dotn_f16(const __half* __restrict__ Ah,
                         const float* __restrict__ kcB, const float* __restrict__ wdB,
                         const float* __restrict__ bc, const float* __restrict__ bd,
                         int C, float* __restrict__ out, int M, int Kp){
    extern __shared__ float sBv[];
    int tid = threadIdx.x;
    int Kc = 64*C, Kt = Kc + 2*C;
    for (int i = tid; i < Kc*3; i += blockDim.x) sBv[i] = kcB[i];
    for (int i = tid; i < C*3; i += blockDim.x){ sBv[Kc*3 + i] = wdB[i]; sBv[(Kc+C)*3 + i] = wdB[i]; }
    __syncthreads();
    int w = tid >> 5, lane = tid & 31;
    int r = blockIdx.x * 8 + w;
    if (r >= M) return;
    float a0=0.f, a1=0.f, a2=0.f;
    const __half* ap = Ah + (size_t)r*Kp;
    for (int k = lane*2; k < Kt; k += 64){
        __half2 h2 = *(const __half2*)(ap + k);
        float av0 = __half2float(h2.x);
        float av1 = __half2float(h2.y);
        a0 += av0 * sBv[k*3+0] + av1 * sBv[(k+1)*3+0];
        a1 += av0 * sBv[k*3+1] + av1 * sBv[(k+1)*3+1];
        a2 += av0 * sBv[k*3+2] + av1 * sBv[(k+1)*3+2];
    }
    for (int off=16; off; off>>=1){
        a0 += __shfl_down_sync(0xffffffffu, a0, off);
        a1 += __shfl_down_sync(0xffffffffu, a1, off);
        a2 += __shfl_down_sync(0xffffffffu, a2, off);
    }
    if (lane == 0){
        out[(size_t)r*3+0] = a0 + bc[0] + bd[0];
        out[(size_t)r*3+1] = a1 + bc[1] + bd[1];
        out[(size_t)r*3+2] = a2 + bc[2] + bd[2];
    }
}

// ---------------- combine (splitK partials + biases + residual) ----------------
__global__ void combine_kernel(const float* __restrict__ oc, int nsplit,
                               const float* __restrict__ bc, const float* __restrict__ bd,
                               const float* __restrict__ prev, float* __restrict__ out, int C){
    int e = blockIdx.x*blockDim.x + threadIdx.x;
    if (e >= 9000*C) return;
    int o = e % C;
    float v = bc[o] + bd[o];
    for (int j = 0; j < nsplit; j++) v += oc[(size_t)j*9000*64 + e];
    if (prev) v += prev[e];
    out[e] = v;
}

__global__ void final_kernel(const float* __restrict__ out4, const float* __restrict__ p1,
                             const float* __restrict__ p0, float* __restrict__ dout){
    int e = blockIdx.x*blockDim.x + threadIdx.x;
    if (e >= NF*3) return;
    int n = e/3, d = e - n*3;
    float pc0 = out4[(n*3+0)*3+d] * 0.25f * (1.0f/16.0f);
    float pc1 = out4[(n*3+1)*3+d] * 0.25f;
    float pc2 = out4[(n*3+2)*3+d] * 0.25f;
    float p_c = p1[e] + pc0;
    dout[e] = p_c;
    dout[9000 + e] = (p_c - p0[e]) / 0.1f;
    dout[18000 + n*6 + d]     = pc1;
    dout[18000 + n*6 + 3 + d] = pc2;
}

// ---------------- launch ----------------
extern "C" void kernel_launch(void* const* d_in, const int* in_sizes, int n_in,
                              void* d_out, int out_size){
    const float* v0e  = (const float*)d_in[1];
    const float* p0   = (const float*)d_in[2];
    const float* v0   = (const float*)d_in[3];
    const float* a    = (const float*)d_in[4];
    const float* other= (const float*)d_in[5];
    const float* box  = (const float*)d_in[6];
    const float* boxf = (const float*)d_in[7];
    const float* bmask= (const float*)d_in[9];
    const float* k0f  = (const float*)d_in[10];
    const float* b0f  = (const float*)d_in[11];
    const float* k0o  = (const float*)d_in[12];
    const float* b0o  = (const float*)d_in[13];
    const float* wdf  = (const float*)d_in[14];
    const float* bdf  = (const float*)d_in[15];
    const float *kc[4], *bcp[4], *wd[4], *bdp[4];
    if (in_sizes[18] == 262144){
        for (int i=0;i<4;i++){
            kc[i]=(const float*)d_in[16+2*i]; bcp[i]=(const float*)d_in[17+2*i];
            wd[i]=(const float*)d_in[24+2*i]; bdp[i]=(const float*)d_in[25+2*i];
        }
    } else {
        for (int i=0;i<4;i++){
            kc[i]=(const float*)d_in[16+4*i]; bcp[i]=(const float*)d_in[17+4*i];
            wd[i]=(const float*)d_in[18+4*i]; bdp[i]=(const float*)d_in[19+4*i];
        }
    }
    float* dout = (float*)d_out;

    float *p1, *feat0, *A0, *Abox, *ocb, *o1, *o2, *fw8, *bw8;
    __half *Ahp, *Bhp, *Blp;
    int *fcnt, *fidx, *fbase, *bcnt, *bidx, *bbase;
    cudaGetSymbolAddress((void**)&p1, g_p1);
    cudaGetSymbolAddress((void**)&feat0, g_feat0);
    cudaGetSymbolAddress((void**)&A0, g_A0);
    cudaGetSymbolAddress((void**)&Abox, g_Abox);
    cudaGetSymbolAddress((void**)&Ahp, g_Ah);
    cudaGetSymbolAddress((void**)&Bhp, g_Bh);
    cudaGetSymbolAddress((void**)&Blp, g_Bl);
    cudaGetSymbolAddress((void**)&ocb, g_oc);
    cudaGetSymbolAddress((void**)&o1, g_out1);
    cudaGetSymbolAddress((void**)&o2, g_out2);
    cudaGetSymbolAddress((void**)&fw8, g_fw8);
    cudaGetSymbolAddress((void**)&bw8, g_bw8);
    cudaGetSymbolAddress((void**)&fcnt, g_fcnt);
    cudaGetSymbolAddress((void**)&fidx, g_fidx);
    cudaGetSymbolAddress((void**)&fbase, g_fbase);
    cudaGetSymbolAddress((void**)&bcnt, g_bcnt);
    cudaGetSymbolAddress((void**)&bidx, g_bidx);
    cudaGetSymbolAddress((void**)&bbase, g_bbase);

    cudaFuncSetAttribute(scatter_big, cudaFuncAttributeMaxDynamicSharedMemorySize, 80000);
    cudaFuncSetAttribute(gemm_mma,    cudaFuncAttributeMaxDynamicSharedMemorySize, 41000);
    cudaFuncSetAttribute(dotn_f16,    cudaFuncAttributeMaxDynamicSharedMemorySize, 52000);

    // Kp padded so splitK=4 chunks are multiples of 32: layer0 6400 (=4*1600), layers1-3 4224 (=4*1056)
    int Kp[4]      = {6400, 4224, 4224, 4224};
    size_t BOff[3] = {0, (size_t)64*6400, (size_t)64*6400 + (size_t)64*4224};
    int Cin[4]     = {96, 64, 64, 64};

    convB3<<<dim3(1600,3), 256>>>(kc[0], wd[0], kc[1], wd[1], kc[2], wd[2], Bhp, Blp);
    prep_kernel<<<(NF+127)/128, 128>>>(p0, v0, a, other, v0e, p1, feat0, dout + 36000);
    neigh_kernel<<<NF, 256>>>(box, NB, p1, bmask, 0, bcnt, bidx, bbase, bw8);
    neigh_kernel<<<NF, 256>>>(p1, NF, p1, nullptr, 1, fcnt, fidx, fbase, fw8);

    // layer 0
    scatter9<<<NF, 96>>>(feat0, fcnt, fidx, fbase, fw8, A0);
    scatter1<<<NF/8, 64>>>(boxf, bcnt, bidx, bbase, bw8, Abox);
    l0gemm<<<188, 256>>>(A0, k0f, b0f, feat0, wdf, bdf, Abox, k0o, b0o, o1);

    float* cur = o1; float* nxt = o2;
    for (int i=0;i<4;i++){
        int ci = Cin[i];
        int F = 3*ci, F4 = F/4;
        int bD = ((F4 + 31)/32)*32;
        scatter_big<<<NF, bD, (size_t)64*F*4>>>(cur, F, ci, fcnt, fidx, fbase, fw8, Ahp, Kp[i]);
        if (i < 3){
            gemm_mma<<<dim3(71,4), 256, 40960>>>(Ahp, Bhp + BOff[i], Blp + BOff[i], ocb, 9000, Kp[i]);
            combine_kernel<<<(9000*64+255)/256, 256>>>(ocb, 4,
                bcp[i], bdp[i], (i==1||i==2) ? cur : nullptr, nxt, 64);
        } else {
            dotn_f16<<<(9000+7)/8, 256, (size_t)4224*3*4>>>(Ahp, kc[3], wd[3],
                bcp[3], bdp[3], 64, nxt, 9000, Kp[3]);
        }
        float* t = cur; cur = nxt; nxt = t;
    }
    final_kernel<<<(NF*3+255)/256, 256>>>(cur, p1, p0, dout);
}

// round 17
// speedup vs baseline: 1.2602x; 1.0198x over previous
#include <cuda_runtime.h>
#include <cuda_fp16.h>
#include <math.h>
#include <stdint.h>

#define NF 3000
#define NB 1500
#define RAD2 9.0f
#define INV_R (1.0f/3.0f)
#define CAP 128
#define EPSF 1e-8f
#define FOUR_OVER_PI 1.2732395447351628f

// ---------------- static device scratch ----------------
__device__ float g_p1[NF*3];
__device__ float g_feat0[NF*9];
__device__ int   g_fcnt[NF];
__device__ int   g_fidx[NF*64];
__device__ int   g_fbase[NF*64];
__device__ float g_fw8[NF*512];
__device__ int   g_bcnt[NF];
__device__ int   g_bidx[NF*64];
__device__ int   g_bbase[NF*64];
__device__ float g_bw8[NF*512];
__device__ float g_A0[9000*192];
__device__ float g_Abox[NF*64];
__device__ __half g_Ah[(size_t)9088*6400];
__device__ __half g_Bh[64*14848];
__device__ __half g_Bl[64*14848];
__device__ float g_oc[4*9000*64];
__device__ float g_out1[9000*96];
__device__ float g_out2[9000*96];

// ---------------- helpers ----------------
__device__ __forceinline__ uint32_t smem_u32(const void* p){
    uint32_t a;
    asm("{ .reg .u64 t; cvta.to.shared.u64 t, %1; cvt.u32.u64 %0, t; }" : "=r"(a) : "l"(p));
    return a;
}
__device__ __forceinline__ void ldsm_x4(uint32_t& r0, uint32_t& r1, uint32_t& r2, uint32_t& r3, uint32_t addr){
    asm volatile("ldmatrix.sync.aligned.m8n8.x4.shared.b16 {%0,%1,%2,%3}, [%4];"
        : "=r"(r0), "=r"(r1), "=r"(r2), "=r"(r3) : "r"(addr));
}
__device__ __forceinline__ void ldsm_x2(uint32_t& r0, uint32_t& r1, uint32_t addr){
    asm volatile("ldmatrix.sync.aligned.m8n8.x2.shared.b16 {%0,%1}, [%2];"
        : "=r"(r0), "=r"(r1) : "r"(addr));
}
__device__ __forceinline__ void mma_f16(float* c, const uint32_t* a, const uint32_t* b){
    asm volatile("mma.sync.aligned.m16n8k16.row.col.f32.f16.f16.f32 "
        "{%0,%1,%2,%3}, {%4,%5,%6,%7}, {%8,%9}, {%0,%1,%2,%3};"
        : "+f"(c[0]), "+f"(c[1]), "+f"(c[2]), "+f"(c[3])
        : "r"(a[0]), "r"(a[1]), "r"(a[2]), "r"(a[3]), "r"(b[0]), "r"(b[1]));
}

// ---------------- geometry ----------------
__device__ __forceinline__ float sgnf(float v){ return (v>0.f)?1.f:((v<0.f)?-1.f:0.f); }

__device__ __forceinline__ void ball_to_cube(float x,float y,float z,float&obx,float&oby,float&obz){
    float sq = x*x+y*y+z*z;
    float norm = sqrtf(fmaxf(sq,EPSF));
    float xy_sq = x*x+y*y;
    bool polar = (1.25f*z*z) > xy_sq;
    float s_p = sqrtf(3.0f*norm/(norm+fabsf(z)+EPSF));
    float s_e = norm / sqrtf(fmaxf(xy_sq,EPSF));
    float cx = polar ? x*s_p : x*s_e;
    float cy = polar ? y*s_p : y*s_e;
    float cz = polar ? sgnf(z)*norm : 1.5f*z;
    float nxy = sqrtf(fmaxf(cx*cx+cy*cy,EPSF));
    bool xdom = fabsf(cy) <= fabsf(cx);
    float sx = (fabsf(cx) > EPSF) ? cx : 1.0f;
    float sy = (fabsf(cy) > EPSF) ? cy : 1.0f;
    float bx1 = sgnf(cx)*nxy;
    float by1 = bx1*FOUR_OVER_PI*atanf(cy/sx);
    float by2 = sgnf(cy)*nxy;
    float bx2 = by2*FOUR_OVER_PI*atanf(cx/sy);
    float bx = xdom ? bx1 : bx2;
    float by = xdom ? by1 : by2;
    if (cx*cx+cy*cy < EPSF){ bx=0.f; by=0.f; }
    if (sq < EPSF){ bx=0.f; by=0.f; cz=0.f; }
    obx=bx; oby=by; obz=cz;
}

// ---------------- prep ----------------
__global__ void prep_kernel(const float* __restrict__ p0,const float* __restrict__ v0,
                            const float* __restrict__ a,const float* __restrict__ other,
                            const float* __restrict__ v0e,
                            float* __restrict__ p1,float* __restrict__ feat0,
                            float* __restrict__ outState){
    int i = blockIdx.x*blockDim.x + threadIdx.x;
    if (i >= NF) return;
#pragma unroll
    for (int d=0; d<3; d++){
        float vv0 = v0[i*3+d];
        float v1  = vv0 + 0.1f*a[i*3+d];
        float pp1 = p0[i*3+d] + 0.1f*(vv0+v1)*0.5f;
        p1[i*3+d]        = pp1;
        feat0[i*9+d]     = v1;
        feat0[i*9+3+d]   = other[i*3+d];
        feat0[i*9+6+d]   = v0e[i*3+d];
        outState[i*3+d]  = v0e[i*3+d];
    }
}

// ---------------- merged neighbor search (fluid blocks 0..NF-1, box blocks NF..2NF-1) ----------------
__global__ void neigh2(const float* __restrict__ p1p, const float* __restrict__ boxp,
                       const float* __restrict__ bmask,
                       int* __restrict__ fcnt, int* __restrict__ fidx,
                       int* __restrict__ fbase, float* __restrict__ fw8,
                       int* __restrict__ bcnt, int* __restrict__ bidx,
                       int* __restrict__ bbase, float* __restrict__ bw8){
    __shared__ float cd2[CAP];
    __shared__ int   cid[CAP];
    __shared__ unsigned long long keys[CAP];
    __shared__ int scnt;
    __shared__ int   sM[64];
    __shared__ int   sB[64];
    __shared__ float sW8[64*8];
    __shared__ unsigned skey[64];
    int tid = threadIdx.x;
    bool isFluid = blockIdx.x < NF;
    int n = isFluid ? blockIdx.x : (blockIdx.x - NF);
    const float* pin = isFluid ? p1p : boxp;
    int Mp = isFluid ? NF : NB;
    const float* mask = isFluid ? nullptr : bmask;
    int selfEx = isFluid ? 1 : 0;
    int* cntO = isFluid ? fcnt : bcnt;
    int* idxO = isFluid ? fidx : bidx;
    int* baseO = isFluid ? fbase : bbase;
    float* w8O = isFluid ? fw8 : bw8;

    float qx = p1p[n*3], qy = p1p[n*3+1], qz = p1p[n*3+2];
    if (tid==0) scnt = 0;
    __syncthreads();
    for (int m = tid; m < Mp; m += blockDim.x){
        if (selfEx && m==n) continue;
        if (mask && !(mask[m] > 0.f)) continue;
        float dx = pin[m*3]-qx, dy = pin[m*3+1]-qy, dz = pin[m*3+2]-qz;
        float d2 = dx*dx + dy*dy + dz*dz;
        if (d2 <= RAD2){
            int p = atomicAdd(&scnt, 1);
            if (p < CAP){ cd2[p]=d2; cid[p]=m; }
        }
    }
    __syncthreads();
    int cn = min(scnt, CAP);
    for (int t = tid; t < CAP; t += blockDim.x)
        keys[t] = (t < cn) ? ((((unsigned long long)__float_as_uint(cd2[t]))<<32) | (unsigned)cid[t])
                           : 0xFFFFFFFFFFFFFFFFull;
    __syncthreads();
    for (int k = 2; k <= CAP; k <<= 1){
        for (int j = k>>1; j > 0; j >>= 1){
            if (tid < CAP/2){
                int i = ((tid & ~(j-1)) << 1) | (tid & (j-1));
                int ixj = i | j;
                bool asc = ((i & k) == 0);
                unsigned long long av = keys[i], bv = keys[ixj];
                if ((av > bv) == asc){ keys[i]=bv; keys[ixj]=av; }
            }
            __syncthreads();
        }
    }
    int keep = min(cn, 64);
    if (tid==0) cntO[n] = keep;
    for (int t = tid; t < keep; t += blockDim.x){
        unsigned long long key = keys[t];
        int m = (int)(key & 0xFFFFFFFFull);
        float dx = pin[m*3]-qx, dy = pin[m*3+1]-qy, dz = pin[m*3+2]-qz;
        float ux = dx*INV_R, uy = dy*INV_R, uz = dz*INV_R;
        float r2 = ux*ux + uy*uy + uz*uz;
        float t1 = 1.f - r2;
        float win = fminf(fmaxf(t1*t1*t1, 0.f), 1.f);
        float bx, by, bz;
        ball_to_cube(ux, uy, uz, bx, by, bz);
        float cxx = fminf(fmaxf((bx*0.5f+0.5f)*3.f, 0.f), 3.f);
        float cyy = fminf(fmaxf((by*0.5f+0.5f)*3.f, 0.f), 3.f);
        float czz = fminf(fmaxf((bz*0.5f+0.5f)*3.f, 0.f), 3.f);
        int c0x = min((int)floorf(cxx), 2);
        int c0y = min((int)floorf(cyy), 2);
        int c0z = min((int)floorf(czz), 2);
        float fx = cxx - (float)c0x, fy = cyy - (float)c0y, fz = czz - (float)c0z;
        sM[t] = m;
        sB[t] = (c0x*4 + c0y)*4 + c0z;
        float gx[2] = {1.f-fx, fx}, gy[2] = {1.f-fy, fy}, gz[2] = {1.f-fz, fz};
        int jj = 0;
        for (int i2=0;i2<2;i2++) for (int j2=0;j2<2;j2++) for (int l2=0;l2<2;l2++)
            sW8[t*8 + (jj++)] = gx[i2]*gy[j2]*gz[l2]*win;
    }
    for (int t = tid; t < 64; t += blockDim.x)
        skey[t] = (t < keep) ? (unsigned)((sB[t] << 6) | t) : 0xFFFFFFFFu;
    __syncthreads();
    for (int k = 2; k <= 64; k <<= 1){
        for (int j = k>>1; j > 0; j >>= 1){
            if (tid < 32){
                int i = ((tid & ~(j-1)) << 1) | (tid & (j-1));
                int ixj = i | j;
                bool asc = ((i & k) == 0);
                unsigned av = skey[i], bv = skey[ixj];
                if ((av > bv) == asc){ skey[i]=bv; skey[ixj]=av; }
            }
            __syncthreads();
        }
    }
    for (int t = tid; t < keep; t += blockDim.x){
        int s = (int)(skey[t] & 63u);
        idxO[n*64+t]  = sM[s];
        baseO[n*64+t] = sB[s];
#pragma unroll
        for (int j=0;j<8;j++) w8O[n*512 + t*8 + j] = sW8[s*8 + j];
    }
}

__constant__ int c_coff[8] = {0,1,4,5,16,17,20,21};

// ---------------- scatter layer0 fluid (F=9) ----------------
__global__ void scatter9(const float* __restrict__ feats,
                         const int* __restrict__ cnt, const int* __restrict__ nidx,
                         const int* __restrict__ nbase, const float* __restrict__ nw8,
                         float* __restrict__ A){
    __shared__ float planes[8*576];
    __shared__ float sfeat[64*9];
    __shared__ float sW[512];
    __shared__ int   sBase[64];
    __shared__ int   sIdx[64];
    int n = blockIdx.x, tid = threadIdx.x;
    int cn = cnt[n];
    for (int e = tid; e < 8*576; e += 96) planes[e] = 0.f;
    if (tid < cn){ sIdx[tid] = nidx[n*64+tid]; sBase[tid] = nbase[n*64+tid]; }
    for (int e = tid; e < cn*8; e += 96) sW[e] = nw8[n*512+e];
    __syncthreads();
    for (int e = tid; e < cn*9; e += 96){
        int k = e/9, f = e-k*9;
        sfeat[e] = feats[(size_t)sIdx[k]*9 + f];
    }
    __syncthreads();
    if (tid < 72){
        int j = tid/9, f = tid - j*9;
        int off = c_coff[j];
        float r = 0.f; int prevb = -1;
        for (int k = 0; k < cn; k++){
            int b = sBase[k];
            if (b != prevb){
                if (prevb >= 0) planes[j*576 + (prevb+off)*9 + f] += r;
                prevb = b; r = 0.f;
            }
            r += sW[k*8+j]*sfeat[k*9+f];
        }
        if (prevb >= 0) planes[j*576 + (prevb+off)*9 + f] += r;
    }
    __syncthreads();
    for (int e = tid; e < 576; e += 96){
        int l = e/9, f = e-l*9;
        int s = f/3, c = f-s*3;
        float v = 0.f;
#pragma unroll
        for (int j=0;j<8;j++) v += planes[j*576+e];
        A[(size_t)(n*3+s)*192 + l*3 + c] = v;
    }
}

// ---------------- scatter box (F=1) ----------------
__global__ void scatter1(const float* __restrict__ feats,
                         const int* __restrict__ cnt, const int* __restrict__ nidx,
                         const int* __restrict__ nbase, const float* __restrict__ nw8,
                         float* __restrict__ A){
    __shared__ float planes[8*8*64];
    __shared__ float sF[8*64];
    __shared__ float sW[8*512];
    __shared__ int   sBase[8*64];
    __shared__ int   sCn[8];
    int tid = threadIdx.x, nb = blockIdx.x;
    for (int e = tid; e < 8*8*64; e += 64) planes[e] = 0.f;
    for (int e = tid; e < 8*64; e += 64){
        int q = e>>6, k = e&63;
        int n = nb*8+q;
        if (k==0) sCn[q] = cnt[n];
        int cnq = cnt[n];
        if (k < cnq){ sBase[e] = nbase[n*64+k]; sF[e] = feats[nidx[n*64+k]]; }
    }
    for (int e = tid; e < 8*512; e += 64){
        int q = e>>9, r = e&511;
        sW[e] = nw8[(size_t)(nb*8+q)*512 + r];
    }
    __syncthreads();
    {
        int q = tid>>3, j = tid&7;
        int off = c_coff[j];
        int cnq = sCn[q];
        float r = 0.f; int prevb = -1;
        for (int k = 0; k < cnq; k++){
            int b = sBase[q*64+k];
            if (b != prevb){
                if (prevb >= 0) planes[(q*8+j)*64 + prevb+off] += r;
                prevb = b; r = 0.f;
            }
            r += sW[q*512 + k*8 + j]*sF[q*64+k];
        }
        if (prevb >= 0) planes[(q*8+j)*64 + prevb+off] += r;
    }
    __syncthreads();
    for (int e = tid; e < 512; e += 64){
        int q = e>>6, l = e&63;
        float v = 0.f;
#pragma unroll
        for (int j=0;j<8;j++) v += planes[(q*8+j)*64 + l];
        A[(size_t)(nb*8+q)*64 + l] = v;
    }
}

// ---------------- scatter (big): batched prefetch; A rows [cellacc | hh | hl | zero-pad] ----------------
__global__ void scatter_big(const float* __restrict__ feats, int F, int C,
                            const int* __restrict__ cnt, const int* __restrict__ nidx,
                            const int* __restrict__ nbase, const float* __restrict__ nw8,
                            __half* __restrict__ Ah, int Kp){
    extern __shared__ float acc[];
    __shared__ int sIdx[64]; __shared__ int sBase[64]; __shared__ float sW[512];
    float4* acc4 = (float4*)acc;
    int n = blockIdx.x, tid = threadIdx.x, bd = blockDim.x;
    int F4 = F >> 2;
    int cn = cnt[n];
    for (int e = tid; e < 64*F4; e += bd) acc4[e] = make_float4(0.f,0.f,0.f,0.f);
    for (int e = tid; e < cn; e += bd){ sIdx[e] = nidx[n*64+e]; sBase[e] = nbase[n*64+e]; }
    for (int e = tid; e < cn*8; e += bd) sW[e] = nw8[n*512+e];
    __syncthreads();
    int f4 = tid;
    if (f4 < F4){
        float4 r[8];
        int prevb = -1;
#pragma unroll
        for (int j=0;j<8;j++) r[j] = make_float4(0.f,0.f,0.f,0.f);
        for (int k0 = 0; k0 < cn; k0 += 8){
            int kb = min(8, cn - k0);
            float4 fv[8];
#pragma unroll
            for (int j=0;j<8;j++){
                if (j < kb){
                    float4 t = ((const float4*)(feats + (size_t)sIdx[k0+j]*F))[f4];
                    t.x = fmaxf(t.x,0.f); t.y = fmaxf(t.y,0.f);
                    t.z = fmaxf(t.z,0.f); t.w = fmaxf(t.w,0.f);
                    fv[j] = t;
                }
            }
#pragma unroll
            for (int j=0;j<8;j++){
                if (j < kb){
                    int b = sBase[k0+j];
                    if (b != prevb){
                        if (prevb >= 0){
#pragma unroll
                            for (int q=0;q<8;q++){
                                int ai = (prevb + c_coff[q])*F4 + f4;
                                float4 t = acc4[ai];
                                t.x += r[q].x; t.y += r[q].y; t.z += r[q].z; t.w += r[q].w;
                                acc4[ai] = t;
                            }
                        }
                        prevb = b;
#pragma unroll
                        for (int q=0;q<8;q++) r[q] = make_float4(0.f,0.f,0.f,0.f);
                    }
#pragma unroll
                    for (int q=0;q<8;q++){
                        float w = sW[(k0+j)*8+q];
                        r[q].x += w*fv[j].x; r[q].y += w*fv[j].y;
                        r[q].z += w*fv[j].z; r[q].w += w*fv[j].w;
                    }
                }
            }
        }
        if (prevb >= 0){
#pragma unroll
            for (int q=0;q<8;q++){
                int ai = (prevb + c_coff[q])*F4 + f4;
                float4 t = acc4[ai];
                t.x += r[q].x; t.y += r[q].y; t.z += r[q].z; t.w += r[q].w;
                acc4[ai] = t;
            }
        }
    }
    __syncthreads();
    for (int e4 = tid; e4 < 64*F4; e4 += bd){
        int l = e4 / F4, fl = e4 - l*F4;
        int f = fl*4;
        int s = f / C, c = f - s*C;
        float4 v = acc4[e4];
        size_t base = (size_t)(n*3+s)*Kp + l*C + c;
        *(__half2*)(Ah+base)   = __floats2half2_rn(v.x, v.y);
        *(__half2*)(Ah+base+2) = __floats2half2_rn(v.z, v.w);
    }
    for (int e = tid; e < 3*C; e += bd){
        int s = e / C, c = e - s*C;
        float v = fmaxf(feats[(size_t)n*F + s*C + c], 0.f);
        __half hh = __float2half_rn(v);
        float lo = v - __half2float(hh);
        Ah[(size_t)(n*3+s)*Kp + 64*C + c]     = hh;
        Ah[(size_t)(n*3+s)*Kp + 64*C + C + c] = __float2half_rn(lo);
    }
    int kt = 66*C;
    int pad = Kp - kt;
    if (pad > 0){
        for (int e = tid; e < 3*pad; e += bd){
            int s = e / pad, c = e - s*pad;
            Ah[(size_t)(n*3+s)*Kp + kt + c] = __float2half_rn(0.f);
        }
    }
}

// ---------------- B' conversion (all 3 MMA layers in one launch) ----------------
__global__ void convB3(const float* __restrict__ kc0, const float* __restrict__ wd0,
                       const float* __restrict__ kc1, const float* __restrict__ wd1,
                       const float* __restrict__ kc2, const float* __restrict__ wd2,
                       __half* __restrict__ Bh, __half* __restrict__ Bl){
    int layer = blockIdx.y;
    int C  = (layer==0) ? 96 : 64;
    int Kp = (layer==0) ? 6400 : 4224;
    size_t off = (layer==0) ? 0 : ((layer==1) ? (size_t)64*6400 : (size_t)64*6400 + (size_t)64*4224);
    const float* kc = (layer==0) ? kc0 : ((layer==1) ? kc1 : kc2);
    const float* wd = (layer==0) ? wd0 : ((layer==1) ? wd1 : wd2);
    int e = blockIdx.x*blockDim.x + threadIdx.x;
    if (e >= 64*Kp) return;
    int n = e / Kp, k = e - n*Kp;
    float v = 0.f;
    if (k < 64*C) v = kc[(size_t)k*64 + n];
    else if (k < 64*C + C) v = wd[(size_t)(k - 64*C)*64 + n];
    else if (k < 64*C + 2*C) v = wd[(size_t)(k - 64*C - C)*64 + n];
    __half h = __float2half_rn(v);
    Bh[off + e] = h;
    Bl[off + e] = __float2half_rn(v - __half2float(h));
}

// ---------------- fp16 MMA GEMM: C[M,64] = A[M,K] @ (Bh+Bl)[64,K]^T, splitK via grid.y ----------------
__global__ __launch_bounds__(256) void gemm_mma(const __half* __restrict__ Ah,
                                                const __half* __restrict__ Bh,
                                                const __half* __restrict__ Bl,
                                                float* __restrict__ Cc, int M, int K){
    extern __shared__ __half sm[];
    const int RS = 40;
    const int OFF_BH = 128*RS;
    const int OFF_BL = 128*RS + 64*RS;
    const int BUFSZ  = 128*RS + 2*64*RS;
    int tid = threadIdx.x;
    int bm = blockIdx.x*128;
    int kLen = K / gridDim.y;
    int kBeg = blockIdx.y*kLen;
    int T = kLen >> 5;
    float* Cout = Cc + (size_t)blockIdx.y * M * 64;

    int arow = tid >> 1, ahalf = tid & 1;
    const __half* AG = Ah + (size_t)(bm+arow)*K + kBeg + ahalf*16;
    int brow = tid >> 2, bq = tid & 3;
    const __half* BhG = Bh + (size_t)brow*K + kBeg + bq*8;
    const __half* BlG = Bl + (size_t)brow*K + kBeg + bq*8;

    uint32_t sbase = smem_u32(sm);
    int wid = tid >> 5, lane = tid & 31;
    int wm = wid & 3, wn = wid >> 2;

    uint4 ra0, ra1, rbh, rbl;
    ra0 = *(const uint4*)(AG);     ra1 = *(const uint4*)(AG + 8);
    rbh = *(const uint4*)(BhG);    rbl = *(const uint4*)(BlG);
    {
        __half* buf = sm;
        *(uint4*)(buf + arow*RS + ahalf*16)     = ra0;
        *(uint4*)(buf + arow*RS + ahalf*16 + 8) = ra1;
        *(uint4*)(buf + OFF_BH + brow*RS + bq*8) = rbh;
        *(uint4*)(buf + OFF_BL + brow*RS + bq*8) = rbl;
    }
    __syncthreads();

    float acc[2][4][4];
#pragma unroll
    for (int mt=0;mt<2;mt++)
#pragma unroll
        for (int nt=0;nt<4;nt++)
#pragma unroll
            for (int q=0;q<4;q++) acc[mt][nt][q] = 0.f;

    for (int t = 0; t < T; t++){
        if (t+1 < T){
            ra0 = *(const uint4*)(AG + (size_t)(t+1)*32);
            ra1 = *(const uint4*)(AG + (size_t)(t+1)*32 + 8);
            rbh = *(const uint4*)(BhG + (size_t)(t+1)*32);
            rbl = *(const uint4*)(BlG + (size_t)(t+1)*32);
        }
        uint32_t bufo = (uint32_t)((t & 1) * BUFSZ) * 2;
#pragma unroll
        for (int ks = 0; ks < 2; ks++){
            int k0 = ks*16;
            uint32_t af[2][4];
#pragma unroll
            for (int mt=0;mt<2;mt++){
                int row = wm*32 + mt*16 + (lane & 15);
                int col = k0 + (lane >> 4)*8;
                uint32_t addr = sbase + bufo + (uint32_t)(row*RS + col)*2;
                ldsm_x4(af[mt][0], af[mt][1], af[mt][2], af[mt][3], addr);
            }
            uint32_t bfh[4][2], bfl[4][2];
#pragma unroll
            for (int nt=0;nt<4;nt++){
                int row = wn*32 + nt*8 + (lane & 7);
                int col = k0 + ((lane >> 3) & 1)*8;
                uint32_t addr = sbase + bufo + (uint32_t)(OFF_BH + row*RS + col)*2;
                ldsm_x2(bfh[nt][0], bfh[nt][1], addr);
                ldsm_x2(bfl[nt][0], bfl[nt][1], addr + (OFF_BL-OFF_BH)*2);
            }
#pragma unroll
            for (int mt=0;mt<2;mt++)
#pragma unroll
                for (int nt=0;nt<4;nt++){
                    mma_f16(acc[mt][nt], af[mt], bfh[nt]);
                    mma_f16(acc[mt][nt], af[mt], bfl[nt]);
                }
        }
        if (t+1 < T){
            __half* buf = sm + ((t+1) & 1) * BUFSZ;
            *(uint4*)(buf + arow*RS + ahalf*16)     = ra0;
            *(uint4*)(buf + arow*RS + ahalf*16 + 8) = ra1;
            *(uint4*)(buf + OFF_BH + brow*RS + bq*8) = rbh;
            *(uint4*)(buf + OFF_BL + brow*RS + bq*8) = rbl;
            __syncthreads();
        }
    }
#pragma unroll
    for (int mt=0;mt<2;mt++){
#pragma unroll
        for (int nt=0;nt<4;nt++){
            int r0 = bm + wm*32 + mt*16 + (lane >> 2);
            int c0 = wn*32 + nt*8 + (lane & 3)*2;
            if (r0 < M)     *(float2*)&Cout[(size_t)r0*64 + c0]     = make_float2(acc[mt][nt][0], acc[mt][nt][1]);
            if (r0+8 < M)   *(float2*)&Cout[(size_t)(r0+8)*64 + c0] = make_float2(acc[mt][nt][2], acc[mt][nt][3]);
        }
    }
}

// ---------------- layer-0 GEMMs (fluid + box) with fused epilogues -> o1 ----------------
__global__ void l0gemm(const float* __restrict__ A0, const float* __restrict__ k0f,
                       const float* __restrict__ b0f, const float* __restrict__ feat0,
                       const float* __restrict__ wdf, const float* __restrict__ bdf,
                       const float* __restrict__ Abox, const float* __restrict__ k0o,
                       const float* __restrict__ b0o, float* __restrict__ o1){
    __shared__ float As[16][64];
    __shared__ float Bs[16][64];
    int tid = threadIdx.x;
    bool fluid = blockIdx.x < 141;
    const float* A = fluid ? A0 : Abox;
    const float* B = fluid ? k0f : k0o;
    int M = fluid ? 9000 : 3000;
    int K = fluid ? 192 : 64;
    int bm = (fluid ? blockIdx.x : (blockIdx.x - 141)) * 64;
    int tm = tid >> 4, tn = tid & 15;
    float accv[4][4] = {};
    int arow = bm + (tid >> 2);
    int akq  = (tid & 3) * 4;
    int brow = tid >> 4;
    int bcol = (tid & 15) * 4;
    for (int k0 = 0; k0 < K; k0 += 16){
        float4 a4 = make_float4(0.f,0.f,0.f,0.f);
        if (arow < M) a4 = *(const float4*)(A + (size_t)arow*K + k0 + akq);
        float4 b4 = make_float4(0.f,0.f,0.f,0.f);
        if (bcol < 32) b4 = *(const float4*)(B + (size_t)(k0+brow)*32 + bcol);
        __syncthreads();
        int lr = tid >> 2;
        As[akq+0][lr] = a4.x; As[akq+1][lr] = a4.y; As[akq+2][lr] = a4.z; As[akq+3][lr] = a4.w;
        *(float4*)&Bs[brow][bcol] = b4;
        __syncthreads();
#pragma unroll
        for (int kk = 0; kk < 16; kk++){
            float4 av = *(const float4*)&As[kk][tm*4];
            float4 bv = *(const float4*)&Bs[kk][tn*4];
            float ar[4] = {av.x, av.y, av.z, av.w};
            float brr[4] = {bv.x, bv.y, bv.z, bv.w};
#pragma unroll
            for (int i=0;i<4;i++)
#pragma unroll
                for (int j=0;j<4;j++) accv[i][j] += ar[i]*brr[j];
        }
    }
#pragma unroll
    for (int i=0;i<4;i++){
        int r = bm + tm*4 + i;
        if (r >= M) continue;
        float f0=0.f, f1=0.f, f2=0.f;
        if (fluid){
            f0 = feat0[r*3+0]; f1 = feat0[r*3+1]; f2 = feat0[r*3+2];
        }
#pragma unroll
        for (int j=0;j<4;j++){
            int c = tn*4 + j;
            if (c >= 32) continue;
            if (fluid){
                o1[(size_t)r*96 + 32 + c] = accv[i][j] + b0f[c];
                o1[(size_t)r*96 + 64 + c] = bdf[c] + f0*wdf[c] + f1*wdf[32+c] + f2*wdf[64+c];
            } else {
                float v = accv[i][j] + b0o[c];
#pragma unroll
                for (int s=0;s<3;s++) o1[(size_t)(r*3+s)*96 + c] = v;
            }
        }
    }
}

// ---------------- fused layer-4 dot ----------------
__global__ void dotn_f16(const __half* __restrict__ Ah,
                         const float* __restrict__ kcB, const float* __restrict__ wdB,
                         const float* __restrict__ bc, const float* __restrict__ bd,
                         int C, float* __restrict__ out, int M, int Kp){
    extern __shared__ float sBv[];
    int tid = threadIdx.x;
    int Kc = 64*C, Kt = Kc + 2*C;
    for (int i = tid; i < Kc*3; i += blockDim.x) sBv[i] = kcB[i];
    for (int i = tid; i < C*3; i += blockDim.x){ sBv[Kc*3 + i] = wdB[i]; sBv[(Kc+C)*3 + i] = wdB[i]; }
    __syncthreads();
    int w = tid >> 5, lane = tid & 31;
    int r = blockIdx.x * 8 + w;
    if (r >= M) return;
    float a0=0.f, a1=0.f, a2=0.f;
    const __half* ap = Ah + (size_t)r*Kp;
    for (int k = lane*2; k < Kt; k += 64){
        __half2 h2 = *(const __half2*)(ap + k);
        float av0 = __half2float(h2.x);
        float av1 = __half2float(h2.y);
        a0 += av0 * sBv[k*3+0] + av1 * sBv[(k+1)*3+0];
        a1 += av0 * sBv[k*3+1] + av1 * sBv[(k+1)*3+1];
        a2 += av0 * sBv[k*3+2] + av1 * sBv[(k+1)*3+2];
    }
    for (int off=16; off; off>>=1){
        a0 += __shfl_down_sync(0xffffffffu, a0, off);
        a1 += __shfl_down_sync(0xffffffffu, a1, off);
        a2 += __shfl_down_sync(0xffffffffu, a2, off);
    }
    if (lane == 0){
        out[(size_t)r*3+0] = a0 + bc[0] + bd[0];
        out[(size_t)r*3+1] = a1 + bc[1] + bd[1];
        out[(size_t)r*3+2] = a2 + bc[2] + bd[2];
    }
}

// ---------------- combine (splitK partials + biases + residual) ----------------
__global__ void combine_kernel(const float* __restrict__ oc, int nsplit,
                               const float* __restrict__ bc, const float* __restrict__ bd,
                               const float* __restrict__ prev, float* __restrict__ out, int C){
    int e = blockIdx.x*blockDim.x + threadIdx.x;
    if (e >= 9000*C) return;
    int o = e % C;
    float v = bc[o] + bd[o];
    for (int j = 0; j < nsplit; j++) v += oc[(size_t)j*9000*64 + e];
    if (prev) v += prev[e];
    out[e] = v;
}

__global__ void final_kernel(const float* __restrict__ out4, const float* __restrict__ p1,
                             const float* __restrict__ p0, float* __restrict__ dout){
    int e = blockIdx.x*blockDim.x + threadIdx.x;
    if (e >= NF*3) return;
    int n = e/3, d = e - n*3;
    float pc0 = out4[(n*3+0)*3+d] * 0.25f * (1.0f/16.0f);
    float pc1 = out4[(n*3+1)*3+d] * 0.25f;
    float pc2 = out4[(n*3+2)*3+d] * 0.25f;
    float p_c = p1[e] + pc0;
    dout[e] = p_c;
    dout[9000 + e] = (p_c - p0[e]) / 0.1f;
    dout[18000 + n*6 + d]     = pc1;
    dout[18000 + n*6 + 3 + d] = pc2;
}

// ---------------- launch ----------------
extern "C" void kernel_launch(void* const* d_in, const int* in_sizes, int n_in,
                              void* d_out, int out_size){
    const float* v0e  = (const float*)d_in[1];
    const float* p0   = (const float*)d_in[2];
    const float* v0   = (const float*)d_in[3];
    const float* a    = (const float*)d_in[4];
    const float* other= (const float*)d_in[5];
    const float* box  = (const float*)d_in[6];
    const float* boxf = (const float*)d_in[7];
    const float* bmask= (const float*)d_in[9];
    const float* k0f  = (const float*)d_in[10];
    const float* b0f  = (const float*)d_in[11];
    const float* k0o  = (const float*)d_in[12];
    const float* b0o  = (const float*)d_in[13];
    const float* wdf  = (const float*)d_in[14];
    const float* bdf  = (const float*)d_in[15];
    const float *kc[4], *bcp[4], *wd[4], *bdp[4];
    if (in_sizes[18] == 262144){
        for (int i=0;i<4;i++){
            kc[i]=(const float*)d_in[16+2*i]; bcp[i]=(const float*)d_in[17+2*i];
            wd[i]=(const float*)d_in[24+2*i]; bdp[i]=(const float*)d_in[25+2*i];
        }
    } else {
        for (int i=0;i<4;i++){
            kc[i]=(const float*)d_in[16+4*i]; bcp[i]=(const float*)d_in[17+4*i];
            wd[i]=(const float*)d_in[18+4*i]; bdp[i]=(const float*)d_in[19+4*i];
        }
    }
    float* dout = (float*)d_out;

    float *p1, *feat0, *A0, *Abox, *ocb, *o1, *o2, *fw8, *bw8;
    __half *Ahp, *Bhp, *Blp;
    int *fcnt, *fidx, *fbase, *bcnt, *bidx, *bbase;
    cudaGetSymbolAddress((void**)&p1, g_p1);
    cudaGetSymbolAddress((void**)&feat0, g_feat0);
    cudaGetSymbolAddress((void**)&A0, g_A0);
    cudaGetSymbolAddress((void**)&Abox, g_Abox);
    cudaGetSymbolAddress((void**)&Ahp, g_Ah);
    cudaGetSymbolAddress((void**)&Bhp, g_Bh);
    cudaGetSymbolAddress((void**)&Blp, g_Bl);
    cudaGetSymbolAddress((void**)&ocb, g_oc);
    cudaGetSymbolAddress((void**)&o1, g_out1);
    cudaGetSymbolAddress((void**)&o2, g_out2);
    cudaGetSymbolAddress((void**)&fw8, g_fw8);
    cudaGetSymbolAddress((void**)&bw8, g_bw8);
    cudaGetSymbolAddress((void**)&fcnt, g_fcnt);
    cudaGetSymbolAddress((void**)&fidx, g_fidx);
    cudaGetSymbolAddress((void**)&fbase, g_fbase);
    cudaGetSymbolAddress((void**)&bcnt, g_bcnt);
    cudaGetSymbolAddress((void**)&bidx, g_bidx);
    cudaGetSymbolAddress((void**)&bbase, g_bbase);

    cudaFuncSetAttribute(scatter_big, cudaFuncAttributeMaxDynamicSharedMemorySize, 80000);
    cudaFuncSetAttribute(gemm_mma,    cudaFuncAttributeMaxDynamicSharedMemorySize, 41000);
    cudaFuncSetAttribute(dotn_f16,    cudaFuncAttributeMaxDynamicSharedMemorySize, 52000);

    int Kp[4]      = {6400, 4224, 4224, 4224};
    size_t BOff[3] = {0, (size_t)64*6400, (size_t)64*6400 + (size_t)64*4224};
    int Cin[4]     = {96, 64, 64, 64};

    convB3<<<dim3(1600,3), 256>>>(kc[0], wd[0], kc[1], wd[1], kc[2], wd[2], Bhp, Blp);
    prep_kernel<<<(NF+127)/128, 128>>>(p0, v0, a, other, v0e, p1, feat0, dout + 36000);
    neigh2<<<2*NF, 256>>>(p1, box, bmask, fcnt, fidx, fbase, fw8, bcnt, bidx, bbase, bw8);

    // layer 0
    scatter9<<<NF, 96>>>(feat0, fcnt, fidx, fbase, fw8, A0);
    scatter1<<<NF/8, 64>>>(boxf, bcnt, bidx, bbase, bw8, Abox);
    l0gemm<<<188, 256>>>(A0, k0f, b0f, feat0, wdf, bdf, Abox, k0o, b0o, o1);

    float* cur = o1; float* nxt = o2;
    for (int i=0;i<4;i++){
        int ci = Cin[i];
        int F = 3*ci, F4 = F/4;
        int bD = ((F4 + 31)/32)*32;
        scatter_big<<<NF, bD, (size_t)64*F*4>>>(cur, F, ci, fcnt, fidx, fbase, fw8, Ahp, Kp[i]);
        if (i < 3){
            gemm_mma<<<dim3(71,4), 256, 40960>>>(Ahp, Bhp + BOff[i], Blp + BOff[i], ocb, 9000, Kp[i]);
            combine_kernel<<<(9000*64+255)/256, 256>>>(ocb, 4,
                bcp[i], bdp[i], (i==1||i==2) ? cur : nullptr, nxt, 64);
        } else {
            dotn_f16<<<(9000+7)/8, 256, (size_t)4224*3*4>>>(Ahp, kc[3], wd[3],
                bcp[3], bdp[3], 64, nxt, 9000, Kp[3]);
        }
        float* t = cur; cur = nxt; nxt = t;
    }
    final_kernel<<<(NF*3+255)/256, 256>>>(cur, p1, p0, dout);
}